// round 14
// baseline (speedup 1.0000x reference)
#include <cuda_runtime.h>
#include <cuda_bf16.h>
#include <math.h>
#include <stdint.h>

// Problem constants
#define BATCH 2
#define SEQ   2048
#define EMB   2048
#define NHEAD 16
#define NGRP  4
#define HDIM  128
#define FFN   8192
#define TOK   (BATCH*SEQ)          // 4096 rows
#define KVW   (NGRP*HDIM)          // 512

typedef __nv_bfloat16 bf16;

// ---------------------------------------------------------------------------
// PTX helpers (portable sm_80+: cp.async / ldmatrix / mma.sync)
// ---------------------------------------------------------------------------
__device__ __forceinline__ uint32_t smem_to_u32(const void* smem_ptr) {
    uint32_t addr;
    asm("{ .reg .u64 tmp; cvta.to.shared.u64 tmp, %1; cvt.u32.u64 %0, tmp; }"
        : "=r"(addr) : "l"(smem_ptr));
    return addr;
}

#define CP_ASYNC16(dst, src) \
    asm volatile("cp.async.cg.shared.global [%0], [%1], 16;\n" \
                 :: "r"(dst), "l"(src))
#define CP_COMMIT() asm volatile("cp.async.commit_group;\n" ::: "memory")
#define CP_WAIT(N)  asm volatile("cp.async.wait_group %0;\n" :: "n"(N) : "memory")

__device__ __forceinline__ void ldsm_x4(uint32_t* r, uint32_t addr) {
    asm volatile("ldmatrix.sync.aligned.m8n8.x4.shared.b16 {%0,%1,%2,%3}, [%4];\n"
        : "=r"(r[0]), "=r"(r[1]), "=r"(r[2]), "=r"(r[3]) : "r"(addr));
}

__device__ __forceinline__ void ldsm_x4_t(uint32_t* r, uint32_t addr) {
    asm volatile("ldmatrix.sync.aligned.m8n8.x4.trans.shared.b16 {%0,%1,%2,%3}, [%4];\n"
        : "=r"(r[0]), "=r"(r[1]), "=r"(r[2]), "=r"(r[3]) : "r"(addr));
}

__device__ __forceinline__ void mma_bf16(float* c, const uint32_t* a, const uint32_t* b) {
    asm volatile(
        "mma.sync.aligned.m16n8k16.row.col.f32.bf16.bf16.f32 "
        "{%0,%1,%2,%3}, {%4,%5,%6,%7}, {%8,%9}, {%0,%1,%2,%3};\n"
        : "+f"(c[0]), "+f"(c[1]), "+f"(c[2]), "+f"(c[3])
        : "r"(a[0]), "r"(a[1]), "r"(a[2]), "r"(a[3]), "r"(b[0]), "r"(b[1]));
}

__device__ __forceinline__ void mma_s8(int32_t* c, const uint32_t* a, const uint32_t* b) {
    asm volatile(
        "mma.sync.aligned.m16n8k32.row.col.s32.s8.s8.s32 "
        "{%0,%1,%2,%3}, {%4,%5,%6,%7}, {%8,%9}, {%0,%1,%2,%3};\n"
        : "+r"(c[0]), "+r"(c[1]), "+r"(c[2]), "+r"(c[3])
        : "r"(a[0]), "r"(a[1]), "r"(a[2]), "r"(a[3]), "r"(b[0]), "r"(b[1]));
}

__device__ __forceinline__ void split2(float v, bf16& h, bf16& l) {
    h = __float2bfloat16(v);
    l = __float2bfloat16(v - __bfloat162float(h));
}

__device__ __forceinline__ void split_pair(float a, float b, uint32_t& hu, uint32_t& lu) {
    __nv_bfloat162 h = __float22bfloat162_rn(make_float2(a, b));
    float2 back = __bfloat1622float2(h);
    __nv_bfloat162 l = __float22bfloat162_rn(make_float2(a - back.x, b - back.y));
    hu = *reinterpret_cast<uint32_t*>(&h);
    lu = *reinterpret_cast<uint32_t*>(&l);
}

__device__ __forceinline__ float gelu_exact(float a) {
    return 0.5f * a * (1.0f + erff(a * 0.70710678118654752f));
}

// quantize one value given inv-scale: v ≈ s*(q + l/128)
__device__ __forceinline__ void quant2(float v, float inv, int8_t& q, int8_t& l) {
    float t = v * inv;
    float qf = rintf(t);
    qf = fminf(fmaxf(qf, -127.f), 127.f);
    float lf = rintf((t - qf) * 128.f);
    lf = fminf(fmaxf(lf, -127.f), 127.f);
    q = (int8_t)(int)qf;
    l = (int8_t)(int)lf;
}

// ---------------------------------------------------------------------------
// Scratch (device globals; allocation-free per harness rules)
// ---------------------------------------------------------------------------
__device__ __align__(256) bf16 g_xrot_hi[TOK*EMB];
__device__ __align__(256) bf16 g_xrot_lo[TOK*EMB];
__device__ __align__(256) bf16 g_x_hi[TOK*EMB];
__device__ __align__(256) bf16 g_x_lo[TOK*EMB];
__device__ __align__(256) bf16 g_q_hi[TOK*EMB];
__device__ __align__(256) bf16 g_q_lo[TOK*EMB];
__device__ __align__(256) bf16 g_k_hi[TOK*KVW];
__device__ __align__(256) bf16 g_k_lo[TOK*KVW];
__device__ __align__(256) bf16 g_v_hi[TOK*KVW];
__device__ __align__(256) bf16 g_v_lo[TOK*KVW];
__device__ __align__(256) bf16 g_ctx_hi[TOK*EMB];
__device__ __align__(256) bf16 g_ctx_lo[TOK*EMB];
__device__ __align__(256) float g_attn[TOK*EMB];
__device__ __align__(256) float g_h[TOK*EMB];
__device__ __align__(256) bf16 g_act_hi[(size_t)TOK*FFN];
__device__ __align__(256) bf16 g_act_lo[(size_t)TOK*FFN];
__device__ __align__(256) float g_fc[TOK*EMB];
// bf16-split transposed weights
__device__ __align__(256) bf16 g_wqT_hi[EMB*EMB];
__device__ __align__(256) bf16 g_wqT_lo[EMB*EMB];
__device__ __align__(256) bf16 g_wkT_hi[KVW*EMB];
__device__ __align__(256) bf16 g_wkT_lo[KVW*EMB];
__device__ __align__(256) bf16 g_wvT_hi[KVW*EMB];
__device__ __align__(256) bf16 g_wvT_lo[KVW*EMB];
__device__ __align__(256) bf16 g_woT_hi[EMB*EMB];
__device__ __align__(256) bf16 g_woT_lo[EMB*EMB];
__device__ __align__(256) bf16 g_winT_hi[(size_t)2*FFN*EMB];
__device__ __align__(256) bf16 g_winT_lo[(size_t)2*FFN*EMB];
__device__ __align__(256) bf16 g_woutT_hi[(size_t)EMB*FFN];
__device__ __align__(256) bf16 g_woutT_lo[(size_t)EMB*FFN];
// int8 split (FFN path) + per-row scales
__device__ __align__(256) int8_t g_h_q8h[TOK*EMB];
__device__ __align__(256) int8_t g_h_q8l[TOK*EMB];
__device__ __align__(256) float  g_h_sc[TOK];
__device__ __align__(256) int8_t g_act_q8h[(size_t)TOK*FFN];
__device__ __align__(256) int8_t g_act_q8l[(size_t)TOK*FFN];
__device__ __align__(256) float  g_act_sc[TOK];
__device__ __align__(256) int8_t g_win_q8h[(size_t)2*FFN*EMB];
__device__ __align__(256) int8_t g_win_q8l[(size_t)2*FFN*EMB];
__device__ __align__(256) float  g_win_sc[2*FFN];
__device__ __align__(256) int8_t g_wout_q8h[(size_t)EMB*FFN];
__device__ __align__(256) int8_t g_wout_q8l[(size_t)EMB*FFN];
__device__ __align__(256) float  g_wout_sc[EMB];

// ---------------------------------------------------------------------------
// Transpose + split; optional row-interleave for GeGLU pairing
// ---------------------------------------------------------------------------
__global__ __launch_bounds__(256) void transpose_split_kernel(
        const float* __restrict__ in, bf16* __restrict__ hi, bf16* __restrict__ lo,
        int R, int C, int ilv_half) {
    __shared__ float t[32][33];
    int bx = blockIdx.x * 32, by = blockIdx.y * 32;
    int tx = threadIdx.x & 31, ty = threadIdx.x >> 5;
    #pragma unroll
    for (int i = ty; i < 32; i += 8)
        t[i][tx] = in[(size_t)(by + i) * C + bx + tx];
    __syncthreads();
    #pragma unroll
    for (int i = ty; i < 32; i += 8) {
        float v = t[tx][i];
        bf16 h, l; split2(v, h, l);
        size_t r = (size_t)(bx + i);
        if (ilv_half) r = (r < (size_t)ilv_half) ? 2*r : 2*(r - ilv_half) + 1;
        size_t o = r * R + by + tx;
        hi[o] = h; lo[o] = l;
    }
}

__global__ __launch_bounds__(256) void split_kernel(const float* __restrict__ in,
                                                    bf16* __restrict__ hi,
                                                    bf16* __restrict__ lo, size_t n) {
    size_t idx = (size_t)blockIdx.x * 256 + threadIdx.x;
    if (idx >= n) return;
    bf16 h, l; split2(in[idx], h, l);
    hi[idx] = h; lo[idx] = l;
}

// ---------------------------------------------------------------------------
// RoPE -> split bf16 pair
// ---------------------------------------------------------------------------
__global__ __launch_bounds__(256) void rope_split_kernel(const float* __restrict__ x,
                                                         bf16* __restrict__ hi,
                                                         bf16* __restrict__ lo) {
    int idx = blockIdx.x * 256 + threadIdx.x;
    if (idx >= TOK*EMB) return;
    int t = idx / EMB;
    int e = idx % EMB;
    int n = t % SEQ;
    int d = e % HDIM;
    int j; float partner; float sign;
    if (d < 64) { j = d;      partner = x[idx + 64]; sign = -1.f; }
    else        { j = d - 64; partner = x[idx - 64]; sign =  1.f; }
    float invf = powf(10000.0f, -(float)j / 64.0f);
    float ang = (float)n * invf;
    float c = cosf(ang), s = sinf(ang);
    float v = x[idx] * c + sign * partner * s;
    bf16 h, l; split2(v, h, l);
    hi[idx] = h; lo[idx] = l;
}

// ---------------------------------------------------------------------------
// rowquant: bf16 hi/lo rows -> int8 hi/lo + per-row scale.  grid = rows.
// Kc in {2048, 8192}; 256 threads, 8 elems/thread per 2048-chunk, two passes.
// ---------------------------------------------------------------------------
__global__ __launch_bounds__(256) void rowquant_kernel(
        const bf16* __restrict__ hi, const bf16* __restrict__ lo,
        int8_t* __restrict__ qh, int8_t* __restrict__ ql,
        float* __restrict__ sc, int Kc) {
    const int row = blockIdx.x;
    const int nch = Kc >> 11;
    float amax = 0.f;
    for (int c = 0; c < nch; c++) {
        size_t base = (size_t)row * Kc + c * 2048 + threadIdx.x * 8;
        uint4 hv = *(const uint4*)(hi + base);
        uint4 lv = *(const uint4*)(lo + base);
        const bf16* hp = (const bf16*)&hv; const bf16* lp = (const bf16*)&lv;
        #pragma unroll
        for (int j = 0; j < 8; j++) {
            float v = __bfloat162float(hp[j]) + __bfloat162float(lp[j]);
            amax = fmaxf(amax, fabsf(v));
        }
    }
    __shared__ float red[8];
    for (int o = 16; o > 0; o >>= 1) amax = fmaxf(amax, __shfl_xor_sync(0xffffffffu, amax, o));
    if ((threadIdx.x & 31) == 0) red[threadIdx.x >> 5] = amax;
    __syncthreads();
    __shared__ float s_sc;
    if (threadIdx.x == 0) {
        float t = red[0];
        #pragma unroll
        for (int i = 1; i < 8; i++) t = fmaxf(t, red[i]);
        s_sc = fmaxf(t, 1e-20f) / 127.f;
        if (threadIdx.x == 0) sc[row] = s_sc;
    }
    __syncthreads();
    float inv = 1.f / s_sc;
    for (int c = 0; c < nch; c++) {
        size_t base = (size_t)row * Kc + c * 2048 + threadIdx.x * 8;
        uint4 hv = *(const uint4*)(hi + base);
        uint4 lv = *(const uint4*)(lo + base);
        const bf16* hp = (const bf16*)&hv; const bf16* lp = (const bf16*)&lv;
        int8_t qb[8], lb[8];
        #pragma unroll
        for (int j = 0; j < 8; j++) {
            float v = __bfloat162float(hp[j]) + __bfloat162float(lp[j]);
            quant2(v, inv, qb[j], lb[j]);
        }
        *(uint2*)(qh + base) = *(uint2*)qb;
        *(uint2*)(ql + base) = *(uint2*)lb;
    }
}

// ---------------------------------------------------------------------------
// bf16-split tensor-core GEMM (QKV / O proj).  Unchanged from R11 (proven).
// ---------------------------------------------------------------------------
#define WST_B    80
#define OP_BYTES (128*WST_B)
#define STAGE_B  (4*OP_BYTES)
#define MG_SMEM  (2*STAGE_B)     // 81920 per CTA -> 2 CTAs/SM

__global__ __launch_bounds__(256, 2) void mma_gemm(
        const bf16* __restrict__ Ahi, const bf16* __restrict__ Alo,
        const bf16* __restrict__ Bhi, const bf16* __restrict__ Blo,
        float* __restrict__ C, bf16* __restrict__ Ch, bf16* __restrict__ Cl,
        int M, int N, int K, int mode) {
    extern __shared__ char smem[];
    const uint32_t sb = smem_to_u32(smem);
    const int tid = threadIdx.x;
    const int m0 = blockIdx.x * 128, n0 = blockIdx.y * 128;
    const int warp = tid >> 5, lane = tid & 31;
    const int wm = warp & 1, wn = warp >> 1;

    const bf16* srcs[4] = { Ahi + (size_t)m0 * K, Alo + (size_t)m0 * K,
                            Bhi + (size_t)n0 * K, Blo + (size_t)n0 * K };

    float acc[4][4][4];
    #pragma unroll
    for (int i = 0; i < 4; i++)
        #pragma unroll
        for (int j = 0; j < 4; j++)
            #pragma unroll
            for (int r = 0; r < 4; r++) acc[i][j][r] = 0.f;

    const int S = K >> 5;
    const int lA_row = lane & 15, lA_k = lane >> 4;
    const int lB_row = ((lane >> 4) << 3) + (lane & 7);
    const int lB_k = (lane >> 3) & 1;

    auto issue_stage = [&](int s) {
        const uint32_t bufb = sb + (uint32_t)(s & 1) * STAGE_B;
        const int k0 = s << 5;
        #pragma unroll
        for (int it = 0; it < 8; it++) {
            int idx = tid + (it << 8);
            int op = it >> 1;
            int j = idx & 511;
            int row = j >> 2, ch = j & 3;
            const bf16* src = srcs[op] + (size_t)row * K + k0 + ch * 8;
            uint32_t dst = bufb + (uint32_t)(op * OP_BYTES + row * WST_B + ch * 16);
            CP_ASYNC16(dst, src);
        }
    };

    issue_stage(0); CP_COMMIT();

    for (int s = 0; s < S; s++) {
        if (s + 1 < S) {
            issue_stage(s + 1);
            CP_COMMIT();
            CP_WAIT(1);
        } else {
            CP_WAIT(0);
        }
        __syncthreads();

        const uint32_t base = sb + (uint32_t)(s & 1) * STAGE_B;
        #pragma unroll
        for (int k16 = 0; k16 < 2; k16++) {
            uint32_t bh[4][2], bl[4][2];
            #pragma unroll
            for (int np = 0; np < 2; np++) {
                uint32_t rb = base + 2 * OP_BYTES
                            + (uint32_t)((wn * 32 + np * 16 + lB_row) * WST_B)
                            + k16 * 32 + lB_k * 16;
                uint32_t t4[4];
                ldsm_x4(t4, rb);
                bh[np*2][0] = t4[0]; bh[np*2][1] = t4[1];
                bh[np*2+1][0] = t4[2]; bh[np*2+1][1] = t4[3];
                ldsm_x4(t4, rb + OP_BYTES);
                bl[np*2][0] = t4[0]; bl[np*2][1] = t4[1];
                bl[np*2+1][0] = t4[2]; bl[np*2+1][1] = t4[3];
            }
            #pragma unroll
            for (int mt = 0; mt < 4; mt++) {
                uint32_t ah[4], al[4];
                uint32_t ra = base + (uint32_t)((wm * 64 + mt * 16 + lA_row) * WST_B)
                            + k16 * 32 + lA_k * 16;
                ldsm_x4(ah, ra);
                ldsm_x4(al, ra + OP_BYTES);
                #pragma unroll
                for (int nt = 0; nt < 4; nt++) {
                    mma_bf16(acc[mt][nt], ah, bh[nt]);
                    mma_bf16(acc[mt][nt], ah, bl[nt]);
                    mma_bf16(acc[mt][nt], al, bh[nt]);
                }
            }
        }
        __syncthreads();
    }

    #pragma unroll
    for (int mt = 0; mt < 4; mt++) {
        int m = m0 + wm * 64 + mt * 16 + (lane >> 2);
        #pragma unroll
        for (int nt = 0; nt < 4; nt++) {
            int n = n0 + wn * 32 + nt * 8 + 2 * (lane & 3);
            if (mode == 0) {
                *(float2*)(C + (size_t)m * N + n) =
                    make_float2(acc[mt][nt][0], acc[mt][nt][1]);
                *(float2*)(C + (size_t)(m + 8) * N + n) =
                    make_float2(acc[mt][nt][2], acc[mt][nt][3]);
            } else {
                uint32_t hu, lu;
                split_pair(acc[mt][nt][0], acc[mt][nt][1], hu, lu);
                *(uint32_t*)(Ch + (size_t)m * N + n) = hu;
                *(uint32_t*)(Cl + (size_t)m * N + n) = lu;
                split_pair(acc[mt][nt][2], acc[mt][nt][3], hu, lu);
                *(uint32_t*)(Ch + (size_t)(m + 8) * N + n) = hu;
                *(uint32_t*)(Cl + (size_t)(m + 8) * N + n) = lu;
            }
        }
    }
}

// ---------------------------------------------------------------------------
// int8-split tensor-core GEMM (FFN path): C = A @ BT^T with x = s(h + l/128).
// 3 IMMAs (hh->acc1, hl+lh->acc2) per 32-K; dequant sA*sB*(acc1+acc2/128).
// Tile 128x64, K-chunk 64, 8 warps (warp 32x32), 2-stage, 2 CTAs/SM.
// mode: 0 = fp32 C; 2 = GeGLU epilogue -> bf16 hi/lo act width N/2.
// s8-k32 fragments are byte-identical to bf16-k16 fragments, so ldmatrix
// addressing is reused with "unit = 2 int8".
// ---------------------------------------------------------------------------
#define I_WST   80                 // 64B data + 16 pad
#define I_AOP   (128*I_WST)        // 10240
#define I_BOP   (64*I_WST)         // 5120
#define I_STAGE (2*I_AOP + 2*I_BOP) // 30720
#define IG_SMEM (2*I_STAGE)        // 61440 per CTA -> 2 CTAs/SM

__global__ __launch_bounds__(256, 2) void imma_gemm(
        const int8_t* __restrict__ Ahq, const int8_t* __restrict__ Alq,
        const float* __restrict__ sA,
        const int8_t* __restrict__ Bhq, const int8_t* __restrict__ Blq,
        const float* __restrict__ sB,
        float* __restrict__ C, bf16* __restrict__ Ch, bf16* __restrict__ Cl,
        int M, int N, int K, int mode) {
    extern __shared__ char smem[];
    const uint32_t sb = smem_to_u32(smem);
    const int tid = threadIdx.x;
    const int m0 = blockIdx.x * 128, n0 = blockIdx.y * 64;
    const int warp = tid >> 5, lane = tid & 31;
    const int wm = warp & 3, wn = warp >> 2;

    int32_t acc1[2][4][4], acc2[2][4][4];
    #pragma unroll
    for (int i = 0; i < 2; i++)
        #pragma unroll
        for (int j = 0; j < 4; j++)
            #pragma unroll
            for (int r = 0; r < 4; r++) { acc1[i][j][r] = 0; acc2[i][j][r] = 0; }

    const int S = K >> 6;
    const int lA_row = lane & 15, lA_k = lane >> 4;
    const int lB_row = ((lane >> 4) << 3) + (lane & 7);
    const int lB_k = (lane >> 3) & 1;

    auto issue_stage = [&](int s) {
        const uint32_t bufb = sb + (uint32_t)(s & 1) * I_STAGE;
        const int k0 = s << 6;
        #pragma unroll
        for (int it = 0; it < 6; it++) {
            int idx = tid + (it << 8);        // 0..1535
            if (idx < 1024) {
                int arr = idx >> 9;           // 0=Ah,1=Al
                int j = idx & 511;
                int row = j >> 2, ch = j & 3;
                const int8_t* src = (arr ? Alq : Ahq)
                                  + (size_t)(m0 + row) * K + k0 + ch * 16;
                uint32_t dst = bufb + (uint32_t)(arr * I_AOP + row * I_WST + ch * 16);
                CP_ASYNC16(dst, src);
            } else {
                int j2 = idx - 1024;
                int arr = j2 >> 8;            // 0=Bh,1=Bl
                int j = j2 & 255;
                int row = j >> 2, ch = j & 3;
                const int8_t* src = (arr ? Blq : Bhq)
                                  + (size_t)(n0 + row) * K + k0 + ch * 16;
                uint32_t dst = bufb + (uint32_t)(2 * I_AOP + arr * I_BOP
                                                 + row * I_WST + ch * 16);
                CP_ASYNC16(dst, src);
            }
        }
    };

    issue_stage(0); CP_COMMIT();

    for (int s = 0; s < S; s++) {
        if (s + 1 < S) {
            issue_stage(s + 1);
            CP_COMMIT();
            CP_WAIT(1);
        } else {
            CP_WAIT(0);
        }
        __syncthreads();

        const uint32_t base = sb + (uint32_t)(s & 1) * I_STAGE;
        #pragma unroll
        for (int ksub = 0; ksub < 2; ksub++) {
            uint32_t bh[4][2], bl[4][2];
            #pragma unroll
            for (int np = 0; np < 2; np++) {
                uint32_t rb = base + 2 * I_AOP
                            + (uint32_t)((wn * 32 + np * 16 + lB_row) * I_WST)
                            + ksub * 32 + lB_k * 16;
                uint32_t t4[4];
                ldsm_x4(t4, rb);
                bh[np*2][0] = t4[0]; bh[np*2][1] = t4[1];
                bh[np*2+1][0] = t4[2]; bh[np*2+1][1] = t4[3];
                ldsm_x4(t4, rb + I_BOP);
                bl[np*2][0] = t4[0]; bl[np*2][1] = t4[1];
                bl[np*2+1][0] = t4[2]; bl[np*2+1][1] = t4[3];
            }
            #pragma unroll
            for (int mt = 0; mt < 2; mt++) {
                uint32_t ah[4], al[4];
                uint32_t ra = base + (uint32_t)((wm * 32 + mt * 16 + lA_row) * I_WST)
                            + ksub * 32 + lA_k * 16;
                ldsm_x4(ah, ra);
                ldsm_x4(al, ra + I_AOP);
                #pragma unroll
                for (int nt = 0; nt < 4; nt++) {
                    mma_s8(acc1[mt][nt], ah, bh[nt]);
                    mma_s8(acc2[mt][nt], ah, bl[nt]);
                    mma_s8(acc2[mt][nt], al, bh[nt]);
                }
            }
        }
        __syncthreads();
    }

    #pragma unroll
    for (int mt = 0; mt < 2; mt++) {
        int m = m0 + wm * 32 + mt * 16 + (lane >> 2);
        float sa0 = sA[m], sa1 = sA[m + 8];
        #pragma unroll
        for (int nt = 0; nt < 4; nt++) {
            int n = n0 + wn * 32 + nt * 8 + 2 * (lane & 3);
            float sb0 = sB[n], sb1 = sB[n + 1];
            float v0 = sa0 * sb0 * ((float)acc1[mt][nt][0] + (float)acc2[mt][nt][0] * 0.0078125f);
            float v1 = sa0 * sb1 * ((float)acc1[mt][nt][1] + (float)acc2[mt][nt][1] * 0.0078125f);
            float v2 = sa1 * sb0 * ((float)acc1[mt][nt][2] + (float)acc2[mt][nt][2] * 0.0078125f);
            float v3 = sa1 * sb1 * ((float)acc1[mt][nt][3] + (float)acc2[mt][nt][3] * 0.0078125f);
            if (mode == 0) {
                *(float2*)(C + (size_t)m * N + n) = make_float2(v0, v1);
                *(float2*)(C + (size_t)(m + 8) * N + n) = make_float2(v2, v3);
            } else {
                int Nh = N >> 1;
                int f = n >> 1;
                float a0 = gelu_exact(v0) * v1;
                float a1 = gelu_exact(v2) * v3;
                bf16 h0, l0, h1, l1;
                split2(a0, h0, l0);
                split2(a1, h1, l1);
                Ch[(size_t)m * Nh + f] = h0;       Cl[(size_t)m * Nh + f] = l0;
                Ch[(size_t)(m + 8) * Nh + f] = h1; Cl[(size_t)(m + 8) * Nh + f] = l1;
            }
        }
    }
}

// ---------------------------------------------------------------------------
// Tensor-core flash attention (bf16 split, causal, GQA) — unchanged from R11.
// ---------------------------------------------------------------------------
#define FSQ_H  0
#define FSQ_L  34816
#define FST0   69632
#define FSTAGE 69632
#define FKL_OFF 17408
#define FVH_OFF 34816
#define FVL_OFF 52224
#define FL_SMEM (FST0 + 2*FSTAGE)   // 208896

__global__ __launch_bounds__(256) void flash_mma_kernel(
        const bf16* __restrict__ Qh, const bf16* __restrict__ Ql,
        const bf16* __restrict__ Kh, const bf16* __restrict__ Kl,
        const bf16* __restrict__ Vh, const bf16* __restrict__ Vl,
        bf16* __restrict__ Oh, bf16* __restrict__ Ol) {
    extern __shared__ char smem[];
    const uint32_t sb = smem_to_u32(smem);
    const int qt = (int)gridDim.x - 1 - (int)blockIdx.x;
    const int hd = blockIdx.y, b = blockIdx.z;
    const int g = hd / (NHEAD / NGRP);
    const int tid = threadIdx.x;
    const int warp = tid >> 5, lane = tid & 31;
    const int lA_row = lane & 15, lA_k = lane >> 4;
    const int lB_row = ((lane >> 4) << 3) + (lane & 7);
    const int lB_k = (lane >> 3) & 1;
    const float SC = 0.08838834764831845f * 1.4426950408889634f;

    {
        const size_t qbase = ((size_t)(b * SEQ + qt * 128)) * EMB + hd * HDIM;
        #pragma unroll
        for (int it = 0; it < 8; it++) {
            int i = tid + (it << 8);
            int row = i >> 4, ch = i & 15;
            size_t ga = qbase + (size_t)row * EMB + ch * 8;
            *(uint4*)(smem + FSQ_H + row * 272 + ch * 16) = *(const uint4*)(Qh + ga);
            *(uint4*)(smem + FSQ_L + row * 272 + ch * 16) = *(const uint4*)(Ql + ga);
        }
    }

    auto issue_kv = [&](int kt) {
        const uint32_t stb = sb + FST0 + (uint32_t)(kt & 1) * FSTAGE;
        const size_t kbase = ((size_t)(b * SEQ + kt * 64)) * KVW + g * HDIM;
        const bf16* gsrc[4] = { Kh + kbase, Kl + kbase, Vh + kbase, Vl + kbase };
        #pragma unroll
        for (int it = 0; it < 16; it++) {
            int idx = tid + (it << 8);
            int arr = it >> 2;
            int j = idx & 1023;
            int row = j >> 4, ch = j & 15;
            const bf16* src = gsrc[arr] + (size_t)row * KVW + ch * 8;
            uint32_t dst = stb + (uint32_t)arr * 17408u + (uint32_t)(row * 272 + ch * 16);
            CP_ASYNC16(dst, src);
        }
    };

    float o[16][4];
    #pragma unroll
    for (int i = 0; i < 16; i++)
        #pragma unroll
        for (int r = 0; r < 4; r++) o[i][r] = 0.f;
    float m0 = -1e30f, m1 = -1e30f, l0 = 0.f, l1 = 0.f;

    const int qg0 = qt * 128 + warp * 16 + (lane >> 2);
    const int qg1 = qg0 + 8;
    const int NT = 2 * qt + 2;

    issue_kv(0);
    CP_COMMIT();

    for (int kt = 0; kt < NT; kt++) {
        if (kt + 1 < NT) {
            issue_kv(kt + 1);
            CP_COMMIT();
            CP_WAIT(1);
        } else {
            CP_WAIT(0);
        }
        __syncthreads();
        const uint32_t stb = sb + FST0 + (uint32_t)(kt & 1) * FSTAGE;

        float s[8][4];
        #pragma unroll
        for (int j = 0; j < 8; j++)
            #pragma unroll
            for (int r = 0; r < 4; r++) s[j][r] = 0.f;

        #pragma unroll
        for (int ks = 0; ks < 8; ks++) {
            uint32_t qh4[4], ql4[4];
            uint32_t ra = sb + FSQ_H + (uint32_t)((warp * 16 + lA_row) * 272)
                        + ks * 32 + lA_k * 16;
            ldsm_x4(qh4, ra);
            ldsm_x4(ql4, ra + (FSQ_L - FSQ_H));
            #pragma unroll
            for (int np = 0; np < 4; np++) {
                uint32_t th[4], tl[4];
                uint32_t rb = stb + (uint32_t)((np * 16 + lB_row) * 272)
                            + ks * 32 + lB_k * 16;
                ldsm_x4(th, rb);
                ldsm_x4(tl, rb + FKL_OFF);
                uint32_t bh0[2] = {th[0], th[1]}, bh1[2] = {th[2], th[3]};
                uint32_t bl0[2] = {tl[0], tl[1]}, bl1[2] = {tl[2], tl[3]};
                mma_bf16(s[2*np],   qh4, bh0);
                mma_bf16(s[2*np],   qh4, bl0);
                mma_bf16(s[2*np],   ql4, bh0);
                mma_bf16(s[2*np+1], qh4, bh1);
                mma_bf16(s[2*np+1], qh4, bl1);
                mma_bf16(s[2*np+1], ql4, bh1);
            }
        }

        float tm0 = -1e30f, tm1 = -1e30f;
        #pragma unroll
        for (int j = 0; j < 8; j++) {
            tm0 = fmaxf(tm0, fmaxf(s[j][0], s[j][1]));
            tm1 = fmaxf(tm1, fmaxf(s[j][2], s[j][3]));
        }
        tm0 = fmaxf(tm0, __shfl_xor_sync(0xffffffffu, tm0, 1));
        tm0 = fmaxf(tm0, __shfl_xor_sync(0xffffffffu, tm0, 2));
        tm1 = fmaxf(tm1, __shfl_xor_sync(0xffffffffu, tm1, 1));
        tm1 = fmaxf(tm1, __shfl_xor_sync(0xffffffffu, tm1, 2));
        float m0n = fmaxf(m0, tm0), m1n = fmaxf(m1, tm1);
        float c0 = exp2f((m0 - m0n) * SC), c1 = exp2f((m1 - m1n) * SC);

        const bool domask = (kt >= 2 * qt);
        float l0a = 0.f, l1a = 0.f;
        #pragma unroll
        for (int j = 0; j < 8; j++) {
            float p0 = exp2f((s[j][0] - m0n) * SC);
            float p1 = exp2f((s[j][1] - m0n) * SC);
            float p2 = exp2f((s[j][2] - m1n) * SC);
            float p3 = exp2f((s[j][3] - m1n) * SC);
            if (domask) {
                int colb = kt * 64 + j * 8 + 2 * (lane & 3);
                if (colb     > qg0) p0 = 0.f;
                if (colb + 1 > qg0) p1 = 0.f;
                if (colb     > qg1) p2 = 0.f;
                if (colb + 1 > qg1) p3 = 0.f;
            }
            s[j][0] = p0; s[j][1] = p1; s[j][2] = p2; s[j][3] = p3;
            l0a += p0 + p1; l1a += p2 + p3;
        }
        l0a += __shfl_xor_sync(0xffffffffu, l0a, 1);
        l0a += __shfl_xor_sync(0xffffffffu, l0a, 2);
        l1a += __shfl_xor_sync(0xffffffffu, l1a, 1);
        l1a += __shfl_xor_sync(0xffffffffu, l1a, 2);
        l0 = l0 * c0 + l0a;
        l1 = l1 * c1 + l1a;
        m0 = m0n; m1 = m1n;

        #pragma unroll
        for (int i = 0; i < 16; i++) {
            o[i][0] *= c0; o[i][1] *= c0; o[i][2] *= c1; o[i][3] *= c1;
        }

        #pragma unroll
        for (int ks = 0; ks < 4; ks++) {
            uint32_t ah[4], al[4];
            split_pair(s[2*ks][0],   s[2*ks][1],   ah[0], al[0]);
            split_pair(s[2*ks][2],   s[2*ks][3],   ah[1], al[1]);
            split_pair(s[2*ks+1][0], s[2*ks+1][1], ah[2], al[2]);
            split_pair(s[2*ks+1][2], s[2*ks+1][3], ah[3], al[3]);
            #pragma unroll
            for (int dp = 0; dp < 8; dp++) {
                uint32_t th[4], tl[4];
                uint32_t rb = stb + FVH_OFF
                            + (uint32_t)((ks * 16 + (lane & 15)) * 272)
                            + (uint32_t)((dp * 16 + ((lane >> 4) << 3)) * 2);
                ldsm_x4_t(th, rb);
                ldsm_x4_t(tl, rb + (FVL_OFF - FVH_OFF));
                uint32_t bh0[2] = {th[0], th[1]}, bh1[2] = {th[2], th[3]};
                uint32_t bl0[2] = {tl[0], tl[1]}, bl1[2] = {tl[2], tl[3]};
                mma_bf16(o[2*dp],   ah, bh0);
                mma_bf16(o[2*dp],   ah, bl0);
                mma_bf16(o[2*dp],   al, bh0);
                mma_bf16(o[2*dp+1], ah, bh1);
                mma_bf16(o[2*dp+1], ah, bl1);
                mma_bf16(o[2*dp+1], al, bh1);
            }
        }
        __syncthreads();
    }

    float inv0 = 1.f / l0, inv1 = 1.f / l1;
    const size_t tok0 = (size_t)(b * SEQ + qt * 128 + warp * 16 + (lane >> 2));
    #pragma unroll
    for (int dt = 0; dt < 16; dt++) {
        int col = hd * HDIM + dt * 8 + 2 * (lane & 3);
        uint32_t hu, lu;
        split_pair(o[dt][0] * inv0, o[dt][1] * inv0, hu, lu);
        *(uint32_t*)(Oh + tok0 * EMB + col) = hu;
        *(uint32_t*)(Ol + tok0 * EMB + col) = lu;
        split_pair(o[dt][2] * inv1, o[dt][3] * inv1, hu, lu);
        *(uint32_t*)(Oh + (tok0 + 8) * EMB + col) = hu;
        *(uint32_t*)(Ol + (tok0 + 8) * EMB + col) = lu;
    }
}

// ---------------------------------------------------------------------------
// out = rmsnorm(a + b) * w ; optional int8 hi/lo + scale outputs
// ---------------------------------------------------------------------------
__global__ __launch_bounds__(256) void add_rmsnorm_kernel(const float* __restrict__ a,
                                                          const float* __restrict__ b,
                                                          const float* __restrict__ w,
                                                          float* __restrict__ out,
                                                          int8_t* __restrict__ qh,
                                                          int8_t* __restrict__ ql,
                                                          float* __restrict__ sc) {
    int row = blockIdx.x;
    const float4* a4 = (const float4*)(a + (size_t)row * EMB);
    const float4* b4 = (const float4*)(b + (size_t)row * EMB);
    const float4* w4 = (const float4*)w;
    float4* o4 = (float4*)(out + (size_t)row * EMB);

    float4 s[2];
    float ss = 0.f;
    #pragma unroll
    for (int i = 0; i < 2; i++) {
        float4 av = a4[threadIdx.x + i * 256];
        float4 bv = b4[threadIdx.x + i * 256];
        s[i] = make_float4(av.x + bv.x, av.y + bv.y, av.z + bv.z, av.w + bv.w);
        ss += s[i].x * s[i].x + s[i].y * s[i].y + s[i].z * s[i].z + s[i].w * s[i].w;
    }
    __shared__ float red[8];
    for (int o = 16; o > 0; o >>= 1) ss += __shfl_xor_sync(0xffffffff, ss, o);
    if ((threadIdx.x & 31) == 0) red[threadIdx.x >> 5] = ss;
    __syncthreads();
    __shared__ float total_s;
    if (threadIdx.x == 0) {
        float t = 0.f;
        #pragma unroll
        for (int i = 0; i < 8; i++) t += red[i];
        total_s = t;
    }
    __syncthreads();
    float rstd = rsqrtf(total_s / (float)EMB + 1e-6f);

    float4 ov[2];
    float amax = 0.f;
    #pragma unroll
    for (int i = 0; i < 2; i++) {
        float4 wv = w4[threadIdx.x + i * 256];
        ov[i] = make_float4(s[i].x * rstd * wv.x, s[i].y * rstd * wv.y,
                            s[i].z * rstd * wv.z, s[i].w * rstd * wv.w);
        o4[threadIdx.x + i * 256] = ov[i];
        amax = fmaxf(amax, fmaxf(fmaxf(fabsf(ov[i].x), fabsf(ov[i].y)),
                                 fmaxf(fabsf(ov[i].z), fabsf(ov[i].w))));
    }
    if (qh) {
        __syncthreads();
        for (int o = 16; o > 0; o >>= 1) amax = fmaxf(amax, __shfl_xor_sync(0xffffffffu, amax, o));
        if ((threadIdx.x & 31) == 0) red[threadIdx.x >> 5] = amax;
        __syncthreads();
        __shared__ float s_sc;
        if (threadIdx.x == 0) {
            float t = red[0];
            #pragma unroll
            for (int i = 1; i < 8; i++) t = fmaxf(t, red[i]);
            s_sc = fmaxf(t, 1e-20f) / 127.f;
            sc[row] = s_sc;
        }
        __syncthreads();
        float inv = 1.f / s_sc;
        #pragma unroll
        for (int i = 0; i < 2; i++) {
            int8_t qb[4], lb[4];
            quant2(ov[i].x, inv, qb[0], lb[0]);
            quant2(ov[i].y, inv, qb[1], lb[1]);
            quant2(ov[i].z, inv, qb[2], lb[2]);
            quant2(ov[i].w, inv, qb[3], lb[3]);
            size_t base = (size_t)row * EMB + (threadIdx.x + i * 256) * 4;
            *(uint32_t*)(qh + base) = *(uint32_t*)qb;
            *(uint32_t*)(ql + base) = *(uint32_t*)lb;
        }
    }
}

// ---------------------------------------------------------------------------
// Launch
// ---------------------------------------------------------------------------
extern "C" void kernel_launch(void* const* d_in, const int* in_sizes, int n_in,
                              void* d_out, int out_size) {
    const float* x       = (const float*)d_in[0];
    const float* wq      = (const float*)d_in[1];
    const float* wk      = (const float*)d_in[2];
    const float* wv      = (const float*)d_in[3];
    const float* wo      = (const float*)d_in[4];
    const float* norm1_w = (const float*)d_in[5];
    const float* norm2_w = (const float*)d_in[6];
    const float* w_in    = (const float*)d_in[7];
    const float* w_out   = (const float*)d_in[8];
    float* out = (float*)d_out;

    bf16 *xrh, *xrl, *xh, *xl, *qh, *ql, *kh, *kl, *vh, *vl, *ctxh, *ctxl;
    bf16 *acth, *actl;
    bf16 *wqh, *wql, *wkh, *wkl, *wvh, *wvl, *woh, *wol, *wih, *wil, *wuh, *wul;
    float *attn, *h, *fc;
    int8_t *hq8h, *hq8l, *actq8h, *actq8l, *winq8h, *winq8l, *woutq8h, *woutq8l;
    float *hsc, *actsc, *winsc, *woutsc;
    cudaGetSymbolAddress((void**)&xrh,  g_xrot_hi);
    cudaGetSymbolAddress((void**)&xrl,  g_xrot_lo);
    cudaGetSymbolAddress((void**)&xh,   g_x_hi);
    cudaGetSymbolAddress((void**)&xl,   g_x_lo);
    cudaGetSymbolAddress((void**)&qh,   g_q_hi);
    cudaGetSymbolAddress((void**)&ql,   g_q_lo);
    cudaGetSymbolAddress((void**)&kh,   g_k_hi);
    cudaGetSymbolAddress((void**)&kl,   g_k_lo);
    cudaGetSymbolAddress((void**)&vh,   g_v_hi);
    cudaGetSymbolAddress((void**)&vl,   g_v_lo);
    cudaGetSymbolAddress((void**)&ctxh, g_ctx_hi);
    cudaGetSymbolAddress((void**)&ctxl, g_ctx_lo);
    cudaGetSymbolAddress((void**)&attn, g_attn);
    cudaGetSymbolAddress((void**)&h,    g_h);
    cudaGetSymbolAddress((void**)&acth, g_act_hi);
    cudaGetSymbolAddress((void**)&actl, g_act_lo);
    cudaGetSymbolAddress((void**)&fc,   g_fc);
    cudaGetSymbolAddress((void**)&wqh,  g_wqT_hi);
    cudaGetSymbolAddress((void**)&wql,  g_wqT_lo);
    cudaGetSymbolAddress((void**)&wkh,  g_wkT_hi);
    cudaGetSymbolAddress((void**)&wkl,  g_wkT_lo);
    cudaGetSymbolAddress((void**)&wvh,  g_wvT_hi);
    cudaGetSymbolAddress((void**)&wvl,  g_wvT_lo);
    cudaGetSymbolAddress((void**)&woh,  g_woT_hi);
    cudaGetSymbolAddress((void**)&wol,  g_woT_lo);
    cudaGetSymbolAddress((void**)&wih,  g_winT_hi);
    cudaGetSymbolAddress((void**)&wil,  g_winT_lo);
    cudaGetSymbolAddress((void**)&wuh,  g_woutT_hi);
    cudaGetSymbolAddress((void**)&wul,  g_woutT_lo);
    cudaGetSymbolAddress((void**)&hq8h,   g_h_q8h);
    cudaGetSymbolAddress((void**)&hq8l,   g_h_q8l);
    cudaGetSymbolAddress((void**)&hsc,    g_h_sc);
    cudaGetSymbolAddress((void**)&actq8h, g_act_q8h);
    cudaGetSymbolAddress((void**)&actq8l, g_act_q8l);
    cudaGetSymbolAddress((void**)&actsc,  g_act_sc);
    cudaGetSymbolAddress((void**)&winq8h, g_win_q8h);
    cudaGetSymbolAddress((void**)&winq8l, g_win_q8l);
    cudaGetSymbolAddress((void**)&winsc,  g_win_sc);
    cudaGetSymbolAddress((void**)&woutq8h,g_wout_q8h);
    cudaGetSymbolAddress((void**)&woutq8l,g_wout_q8l);
    cudaGetSymbolAddress((void**)&woutsc, g_wout_sc);

    cudaFuncSetAttribute(mma_gemm, cudaFuncAttributeMaxDynamicSharedMemorySize,
                         MG_SMEM);
    cudaFuncSetAttribute(imma_gemm, cudaFuncAttributeMaxDynamicSharedMemorySize,
                         IG_SMEM);
    cudaFuncSetAttribute(flash_mma_kernel, cudaFuncAttributeMaxDynamicSharedMemorySize,
                         FL_SMEM);

    // 0. Transpose + split weights (w_in interleaved a/g), then int8 rowquant FFN weights
    transpose_split_kernel<<<dim3(EMB/32,   EMB/32), 256>>>(wq,    wqh, wql, EMB, EMB, 0);
    transpose_split_kernel<<<dim3(KVW/32,   EMB/32), 256>>>(wk,    wkh, wkl, EMB, KVW, 0);
    transpose_split_kernel<<<dim3(KVW/32,   EMB/32), 256>>>(wv,    wvh, wvl, EMB, KVW, 0);
    transpose_split_kernel<<<dim3(EMB/32,   EMB/32), 256>>>(wo,    woh, wol, EMB, EMB, 0);
    transpose_split_kernel<<<dim3(2*FFN/32, EMB/32), 256>>>(w_in,  wih, wil, EMB, 2*FFN, FFN);
    transpose_split_kernel<<<dim3(EMB/32,   FFN/32), 256>>>(w_out, wuh, wul, FFN, EMB, 0);
    rowquant_kernel<<<2*FFN, 256>>>(wih, wil, winq8h, winq8l, winsc, EMB);
    rowquant_kernel<<<EMB,   256>>>(wuh, wul, woutq8h, woutq8l, woutsc, FFN);

    // 1. RoPE (+split) and split(x)
    rope_split_kernel<<<(TOK * EMB + 255) / 256, 256>>>(x, xrh, xrl);
    split_kernel<<<(TOK * EMB + 255) / 256, 256>>>(x, xh, xl, (size_t)TOK * EMB);

    // 2-4. Q/K/V projections (bf16 split)
    mma_gemm<<<dim3(TOK/128, EMB/128), 256, MG_SMEM>>>(xrh, xrl, wqh, wql,
        nullptr, qh, ql, TOK, EMB, EMB, 1);
    mma_gemm<<<dim3(TOK/128, KVW/128), 256, MG_SMEM>>>(xrh, xrl, wkh, wkl,
        nullptr, kh, kl, TOK, KVW, EMB, 1);
    mma_gemm<<<dim3(TOK/128, KVW/128), 256, MG_SMEM>>>(xh,  xl,  wvh, wvl,
        nullptr, vh, vl, TOK, KVW, EMB, 1);

    // 5. Flash attention -> ctx hi/lo
    flash_mma_kernel<<<dim3(SEQ/128, NHEAD, BATCH), 256, FL_SMEM>>>(
        qh, ql, kh, kl, vh, vl, ctxh, ctxl);

    // 6. Output projection (bf16 split, fp32 out)
    mma_gemm<<<dim3(TOK/128, EMB/128), 256, MG_SMEM>>>(ctxh, ctxl, woh, wol,
        attn, nullptr, nullptr, TOK, EMB, EMB, 0);

    // 7. h = rmsnorm(x + attn) * norm1_w  (+ int8 quant with row scale)
    add_rmsnorm_kernel<<<TOK, 256>>>(x, attn, norm1_w, h, hq8h, hq8l, hsc);

    // 8+9. act = geglu(h @ w_in)  (int8 IMMA, GeGLU epilogue -> bf16 pair)
    imma_gemm<<<dim3(TOK/128, 2*FFN/64), 256, IG_SMEM>>>(
        hq8h, hq8l, hsc, winq8h, winq8l, winsc,
        nullptr, acth, actl, TOK, 2*FFN, EMB, 2);

    // 9b. quantize act rows to int8
    rowquant_kernel<<<TOK, 256>>>(acth, actl, actq8h, actq8l, actsc, FFN);

    // 10. fc = act @ w_out  (int8 IMMA, fp32 out)
    imma_gemm<<<dim3(TOK/128, EMB/64), 256, IG_SMEM>>>(
        actq8h, actq8l, actsc, woutq8h, woutq8l, woutsc,
        fc, nullptr, nullptr, TOK, EMB, FFN, 0);

    // 11. out = rmsnorm(h + fc) * norm2_w
    add_rmsnorm_kernel<<<TOK, 256>>>(h, fc, norm2_w, out, nullptr, nullptr, nullptr);
}

// round 15
// speedup vs baseline: 2.8024x; 2.8024x over previous
#include <cuda_runtime.h>
#include <cuda_fp16.h>
#include <math.h>
#include <stdint.h>

// Problem constants
#define BATCH 2
#define SEQ   2048
#define EMB   2048
#define NHEAD 16
#define NGRP  4
#define HDIM  128
#define FFN   8192
#define TOK   (BATCH*SEQ)          // 4096 rows
#define KVW   (NGRP*HDIM)          // 512

typedef __half f16;

// ---------------------------------------------------------------------------
// PTX helpers (portable sm_80+: cp.async / ldmatrix / mma.sync)
// ---------------------------------------------------------------------------
__device__ __forceinline__ uint32_t smem_to_u32(const void* smem_ptr) {
    uint32_t addr;
    asm("{ .reg .u64 tmp; cvta.to.shared.u64 tmp, %1; cvt.u32.u64 %0, tmp; }"
        : "=r"(addr) : "l"(smem_ptr));
    return addr;
}

#define CP_ASYNC16(dst, src) \
    asm volatile("cp.async.cg.shared.global [%0], [%1], 16;\n" \
                 :: "r"(dst), "l"(src))
#define CP_COMMIT() asm volatile("cp.async.commit_group;\n" ::: "memory")
#define CP_WAIT(N)  asm volatile("cp.async.wait_group %0;\n" :: "n"(N) : "memory")

__device__ __forceinline__ void ldsm_x4(uint32_t* r, uint32_t addr) {
    asm volatile("ldmatrix.sync.aligned.m8n8.x4.shared.b16 {%0,%1,%2,%3}, [%4];\n"
        : "=r"(r[0]), "=r"(r[1]), "=r"(r[2]), "=r"(r[3]) : "r"(addr));
}

__device__ __forceinline__ void ldsm_x4_t(uint32_t* r, uint32_t addr) {
    asm volatile("ldmatrix.sync.aligned.m8n8.x4.trans.shared.b16 {%0,%1,%2,%3}, [%4];\n"
        : "=r"(r[0]), "=r"(r[1]), "=r"(r[2]), "=r"(r[3]) : "r"(addr));
}

__device__ __forceinline__ void mma_f16(float* c, const uint32_t* a, const uint32_t* b) {
    asm volatile(
        "mma.sync.aligned.m16n8k16.row.col.f32.f16.f16.f32 "
        "{%0,%1,%2,%3}, {%4,%5,%6,%7}, {%8,%9}, {%0,%1,%2,%3};\n"
        : "+f"(c[0]), "+f"(c[1]), "+f"(c[2]), "+f"(c[3])
        : "r"(a[0]), "r"(a[1]), "r"(a[2]), "r"(a[3]), "r"(b[0]), "r"(b[1]));
}

__device__ __forceinline__ void split2(float v, f16& h, f16& l) {
    h = __float2half_rn(v);
    l = __float2half_rn(v - __half2float(h));
}

// pack float pair -> (hi f16x2, lo f16x2) as uint32
__device__ __forceinline__ void split_pair(float a, float b, uint32_t& hu, uint32_t& lu) {
    __half2 h = __float22half2_rn(make_float2(a, b));
    float2 back = __half22float2(h);
    __half2 l = __float22half2_rn(make_float2(a - back.x, b - back.y));
    hu = *reinterpret_cast<uint32_t*>(&h);
    lu = *reinterpret_cast<uint32_t*>(&l);
}

__device__ __forceinline__ float gelu_exact(float a) {
    return 0.5f * a * (1.0f + erff(a * 0.70710678118654752f));
}

// ---------------------------------------------------------------------------
// Scratch (device globals; allocation-free per harness rules)
// ---------------------------------------------------------------------------
__device__ __align__(256) f16 g_xrot_hi[TOK*EMB];
__device__ __align__(256) f16 g_xrot_lo[TOK*EMB];
__device__ __align__(256) f16 g_x_hi[TOK*EMB];
__device__ __align__(256) f16 g_x_lo[TOK*EMB];
__device__ __align__(256) f16 g_q_hi[TOK*EMB];
__device__ __align__(256) f16 g_q_lo[TOK*EMB];
__device__ __align__(256) f16 g_k_hi[TOK*KVW];
__device__ __align__(256) f16 g_k_lo[TOK*KVW];
__device__ __align__(256) f16 g_v_hi[TOK*KVW];
__device__ __align__(256) f16 g_v_lo[TOK*KVW];
__device__ __align__(256) f16 g_ctx_hi[TOK*EMB];
__device__ __align__(256) f16 g_ctx_lo[TOK*EMB];
__device__ __align__(256) float g_attn[TOK*EMB];
__device__ __align__(256) float g_h[TOK*EMB];
__device__ __align__(256) f16 g_h_hi[TOK*EMB];
__device__ __align__(256) f16 g_h_lo[TOK*EMB];
__device__ __align__(256) f16 g_act_hi[(size_t)TOK*FFN];
__device__ __align__(256) f16 g_act_lo[(size_t)TOK*FFN];
__device__ __align__(256) float g_fc[TOK*EMB];
// transposed weights, fp16 hi ONLY (B-side of all GEMMs)
__device__ __align__(256) f16 g_wqT[EMB*EMB];
__device__ __align__(256) f16 g_wkT[KVW*EMB];
__device__ __align__(256) f16 g_wvT[KVW*EMB];
__device__ __align__(256) f16 g_woT[EMB*EMB];
__device__ __align__(256) f16 g_winT[(size_t)2*FFN*EMB];
__device__ __align__(256) f16 g_woutT[(size_t)EMB*FFN];

// ---------------------------------------------------------------------------
// Transpose -> fp16 hi only; optional row-interleave for GeGLU pairing
// ---------------------------------------------------------------------------
__global__ __launch_bounds__(256) void transpose_h_kernel(
        const float* __restrict__ in, f16* __restrict__ hi,
        int R, int C, int ilv_half) {
    __shared__ float t[32][33];
    int bx = blockIdx.x * 32, by = blockIdx.y * 32;
    int tx = threadIdx.x & 31, ty = threadIdx.x >> 5;
    #pragma unroll
    for (int i = ty; i < 32; i += 8)
        t[i][tx] = in[(size_t)(by + i) * C + bx + tx];
    __syncthreads();
    #pragma unroll
    for (int i = ty; i < 32; i += 8) {
        float v = t[tx][i];
        size_t r = (size_t)(bx + i);
        if (ilv_half) r = (r < (size_t)ilv_half) ? 2*r : 2*(r - ilv_half) + 1;
        hi[r * R + by + tx] = __float2half_rn(v);
    }
}

__global__ __launch_bounds__(256) void split_kernel(const float* __restrict__ in,
                                                    f16* __restrict__ hi,
                                                    f16* __restrict__ lo, size_t n) {
    size_t idx = (size_t)blockIdx.x * 256 + threadIdx.x;
    if (idx >= n) return;
    f16 h, l; split2(in[idx], h, l);
    hi[idx] = h; lo[idx] = l;
}

// ---------------------------------------------------------------------------
// RoPE -> split fp16 pair
// ---------------------------------------------------------------------------
__global__ __launch_bounds__(256) void rope_split_kernel(const float* __restrict__ x,
                                                         f16* __restrict__ hi,
                                                         f16* __restrict__ lo) {
    int idx = blockIdx.x * 256 + threadIdx.x;
    if (idx >= TOK*EMB) return;
    int t = idx / EMB;
    int e = idx % EMB;
    int n = t % SEQ;
    int d = e % HDIM;
    int j; float partner; float sign;
    if (d < 64) { j = d;      partner = x[idx + 64]; sign = -1.f; }
    else        { j = d - 64; partner = x[idx - 64]; sign =  1.f; }
    float invf = powf(10000.0f, -(float)j / 64.0f);
    float ang = (float)n * invf;
    float c = cosf(ang), s = sinf(ang);
    float v = x[idx] * c + sign * partner * s;
    f16 h, l; split2(v, h, l);
    hi[idx] = h; lo[idx] = l;
}

// ---------------------------------------------------------------------------
// fp16 2-term tensor-core GEMM: C = (Ah+Al) @ Bh^T.  128x128 tile, Kstep 32,
// 8 warps, 2-stage cp.async, 2 CTAs/SM.  Only 3 operands in smem (Ah,Al,Bh).
// mode: 0 = fp32 C; 1 = f16 hi/lo split; 2 = GeGLU epilogue width N/2.
// ---------------------------------------------------------------------------
#define WST_B    80
#define OP_BYTES (128*WST_B)
#define STAGE_B  (3*OP_BYTES)    // 30720
#define MG_SMEM  (2*STAGE_B)     // 61440 per CTA -> 2 CTAs/SM

__global__ __launch_bounds__(256, 2) void mma_gemm(
        const f16* __restrict__ Ahi, const f16* __restrict__ Alo,
        const f16* __restrict__ Bhi,
        float* __restrict__ C, f16* __restrict__ Ch, f16* __restrict__ Cl,
        int M, int N, int K, int mode) {
    extern __shared__ char smem[];
    const uint32_t sb = smem_to_u32(smem);
    const int tid = threadIdx.x;
    const int m0 = blockIdx.x * 128, n0 = blockIdx.y * 128;
    const int warp = tid >> 5, lane = tid & 31;
    const int wm = warp & 1, wn = warp >> 1;

    const f16* srcs[3] = { Ahi + (size_t)m0 * K, Alo + (size_t)m0 * K,
                           Bhi + (size_t)n0 * K };

    float acc[4][4][4];
    #pragma unroll
    for (int i = 0; i < 4; i++)
        #pragma unroll
        for (int j = 0; j < 4; j++)
            #pragma unroll
            for (int r = 0; r < 4; r++) acc[i][j][r] = 0.f;

    const int S = K >> 5;
    const int lA_row = lane & 15, lA_k = lane >> 4;
    const int lB_row = ((lane >> 4) << 3) + (lane & 7);
    const int lB_k = (lane >> 3) & 1;

    auto issue_stage = [&](int s) {
        const uint32_t bufb = sb + (uint32_t)(s & 1) * STAGE_B;
        const int k0 = s << 5;
        #pragma unroll
        for (int it = 0; it < 6; it++) {
            int idx = tid + (it << 8);       // 0..1535
            int op = idx >> 9;               // 0=Ah,1=Al,2=Bh
            int j = idx & 511;
            int row = j >> 2, ch = j & 3;
            const f16* src = srcs[op] + (size_t)row * K + k0 + ch * 8;
            uint32_t dst = bufb + (uint32_t)(op * OP_BYTES + row * WST_B + ch * 16);
            CP_ASYNC16(dst, src);
        }
    };

    issue_stage(0); CP_COMMIT();

    for (int s = 0; s < S; s++) {
        if (s + 1 < S) {
            issue_stage(s + 1);
            CP_COMMIT();
            CP_WAIT(1);
        } else {
            CP_WAIT(0);
        }
        __syncthreads();

        const uint32_t base = sb + (uint32_t)(s & 1) * STAGE_B;
        #pragma unroll
        for (int k16 = 0; k16 < 2; k16++) {
            uint32_t bh[4][2];
            #pragma unroll
            for (int np = 0; np < 2; np++) {
                uint32_t rb = base + 2 * OP_BYTES
                            + (uint32_t)((wn * 32 + np * 16 + lB_row) * WST_B)
                            + k16 * 32 + lB_k * 16;
                uint32_t t4[4];
                ldsm_x4(t4, rb);
                bh[np*2][0] = t4[0]; bh[np*2][1] = t4[1];
                bh[np*2+1][0] = t4[2]; bh[np*2+1][1] = t4[3];
            }
            #pragma unroll
            for (int mt = 0; mt < 4; mt++) {
                uint32_t ah[4], al[4];
                uint32_t ra = base + (uint32_t)((wm * 64 + mt * 16 + lA_row) * WST_B)
                            + k16 * 32 + lA_k * 16;
                ldsm_x4(ah, ra);
                ldsm_x4(al, ra + OP_BYTES);
                #pragma unroll
                for (int nt = 0; nt < 4; nt++) {
                    mma_f16(acc[mt][nt], ah, bh[nt]);
                    mma_f16(acc[mt][nt], al, bh[nt]);
                }
            }
        }
        __syncthreads();
    }

    #pragma unroll
    for (int mt = 0; mt < 4; mt++) {
        int m = m0 + wm * 64 + mt * 16 + (lane >> 2);
        #pragma unroll
        for (int nt = 0; nt < 4; nt++) {
            int n = n0 + wn * 32 + nt * 8 + 2 * (lane & 3);
            if (mode == 0) {
                *(float2*)(C + (size_t)m * N + n) =
                    make_float2(acc[mt][nt][0], acc[mt][nt][1]);
                *(float2*)(C + (size_t)(m + 8) * N + n) =
                    make_float2(acc[mt][nt][2], acc[mt][nt][3]);
            } else if (mode == 1) {
                uint32_t hu, lu;
                split_pair(acc[mt][nt][0], acc[mt][nt][1], hu, lu);
                *(uint32_t*)(Ch + (size_t)m * N + n) = hu;
                *(uint32_t*)(Cl + (size_t)m * N + n) = lu;
                split_pair(acc[mt][nt][2], acc[mt][nt][3], hu, lu);
                *(uint32_t*)(Ch + (size_t)(m + 8) * N + n) = hu;
                *(uint32_t*)(Cl + (size_t)(m + 8) * N + n) = lu;
            } else {
                // GeGLU: (c0,c1)=(a,g) for row m; (c2,c3) for row m+8
                int Nh = N >> 1;
                int f = n >> 1;
                float v0 = gelu_exact(acc[mt][nt][0]) * acc[mt][nt][1];
                float v1 = gelu_exact(acc[mt][nt][2]) * acc[mt][nt][3];
                f16 h0, l0, h1, l1;
                split2(v0, h0, l0);
                split2(v1, h1, l1);
                Ch[(size_t)m * Nh + f] = h0;       Cl[(size_t)m * Nh + f] = l0;
                Ch[(size_t)(m + 8) * Nh + f] = h1; Cl[(size_t)(m + 8) * Nh + f] = l1;
            }
        }
    }
}

// ---------------------------------------------------------------------------
// Tensor-core flash attention (fp16 split, causal, GQA).  3-term (full
// precision) — unchanged structure from R11, dtype bf16 -> fp16.
// ---------------------------------------------------------------------------
#define FSQ_H  0
#define FSQ_L  34816
#define FST0   69632
#define FSTAGE 69632          // per-stage: KH,KL,VH,VL each 64*272=17408
#define FKL_OFF 17408
#define FVH_OFF 34816
#define FVL_OFF 52224
#define FL_SMEM (FST0 + 2*FSTAGE)   // 208896

__global__ __launch_bounds__(256) void flash_mma_kernel(
        const f16* __restrict__ Qh, const f16* __restrict__ Ql,
        const f16* __restrict__ Kh, const f16* __restrict__ Kl,
        const f16* __restrict__ Vh, const f16* __restrict__ Vl,
        f16* __restrict__ Oh, f16* __restrict__ Ol) {
    extern __shared__ char smem[];
    const uint32_t sb = smem_to_u32(smem);
    const int qt = (int)gridDim.x - 1 - (int)blockIdx.x;  // big tiles first
    const int hd = blockIdx.y, b = blockIdx.z;
    const int g = hd / (NHEAD / NGRP);
    const int tid = threadIdx.x;
    const int warp = tid >> 5, lane = tid & 31;
    const int lA_row = lane & 15, lA_k = lane >> 4;
    const int lB_row = ((lane >> 4) << 3) + (lane & 7);
    const int lB_k = (lane >> 3) & 1;
    const float SC = 0.08838834764831845f * 1.4426950408889634f;  // scale*log2e

    {
        const size_t qbase = ((size_t)(b * SEQ + qt * 128)) * EMB + hd * HDIM;
        #pragma unroll
        for (int it = 0; it < 8; it++) {
            int i = tid + (it << 8);
            int row = i >> 4, ch = i & 15;
            size_t ga = qbase + (size_t)row * EMB + ch * 8;
            *(uint4*)(smem + FSQ_H + row * 272 + ch * 16) = *(const uint4*)(Qh + ga);
            *(uint4*)(smem + FSQ_L + row * 272 + ch * 16) = *(const uint4*)(Ql + ga);
        }
    }

    auto issue_kv = [&](int kt) {
        const uint32_t stb = sb + FST0 + (uint32_t)(kt & 1) * FSTAGE;
        const size_t kbase = ((size_t)(b * SEQ + kt * 64)) * KVW + g * HDIM;
        const f16* gsrc[4] = { Kh + kbase, Kl + kbase, Vh + kbase, Vl + kbase };
        #pragma unroll
        for (int it = 0; it < 16; it++) {
            int idx = tid + (it << 8);
            int arr = it >> 2;
            int j = idx & 1023;
            int row = j >> 4, ch = j & 15;
            const f16* src = gsrc[arr] + (size_t)row * KVW + ch * 8;
            uint32_t dst = stb + (uint32_t)arr * 17408u + (uint32_t)(row * 272 + ch * 16);
            CP_ASYNC16(dst, src);
        }
    };

    float o[16][4];
    #pragma unroll
    for (int i = 0; i < 16; i++)
        #pragma unroll
        for (int r = 0; r < 4; r++) o[i][r] = 0.f;
    float m0 = -1e30f, m1 = -1e30f, l0 = 0.f, l1 = 0.f;

    const int qg0 = qt * 128 + warp * 16 + (lane >> 2);
    const int qg1 = qg0 + 8;
    const int NT = 2 * qt + 2;

    issue_kv(0);
    CP_COMMIT();

    for (int kt = 0; kt < NT; kt++) {
        if (kt + 1 < NT) {
            issue_kv(kt + 1);
            CP_COMMIT();
            CP_WAIT(1);
        } else {
            CP_WAIT(0);
        }
        __syncthreads();
        const uint32_t stb = sb + FST0 + (uint32_t)(kt & 1) * FSTAGE;

        float s[8][4];
        #pragma unroll
        for (int j = 0; j < 8; j++)
            #pragma unroll
            for (int r = 0; r < 4; r++) s[j][r] = 0.f;

        #pragma unroll
        for (int ks = 0; ks < 8; ks++) {
            uint32_t qh4[4], ql4[4];
            uint32_t ra = sb + FSQ_H + (uint32_t)((warp * 16 + lA_row) * 272)
                        + ks * 32 + lA_k * 16;
            ldsm_x4(qh4, ra);
            ldsm_x4(ql4, ra + (FSQ_L - FSQ_H));
            #pragma unroll
            for (int np = 0; np < 4; np++) {
                uint32_t th[4], tl[4];
                uint32_t rb = stb + (uint32_t)((np * 16 + lB_row) * 272)
                            + ks * 32 + lB_k * 16;
                ldsm_x4(th, rb);
                ldsm_x4(tl, rb + FKL_OFF);
                uint32_t bh0[2] = {th[0], th[1]}, bh1[2] = {th[2], th[3]};
                uint32_t bl0[2] = {tl[0], tl[1]}, bl1[2] = {tl[2], tl[3]};
                mma_f16(s[2*np],   qh4, bh0);
                mma_f16(s[2*np],   qh4, bl0);
                mma_f16(s[2*np],   ql4, bh0);
                mma_f16(s[2*np+1], qh4, bh1);
                mma_f16(s[2*np+1], qh4, bl1);
                mma_f16(s[2*np+1], ql4, bh1);
            }
        }

        float tm0 = -1e30f, tm1 = -1e30f;
        #pragma unroll
        for (int j = 0; j < 8; j++) {
            tm0 = fmaxf(tm0, fmaxf(s[j][0], s[j][1]));
            tm1 = fmaxf(tm1, fmaxf(s[j][2], s[j][3]));
        }
        tm0 = fmaxf(tm0, __shfl_xor_sync(0xffffffffu, tm0, 1));
        tm0 = fmaxf(tm0, __shfl_xor_sync(0xffffffffu, tm0, 2));
        tm1 = fmaxf(tm1, __shfl_xor_sync(0xffffffffu, tm1, 1));
        tm1 = fmaxf(tm1, __shfl_xor_sync(0xffffffffu, tm1, 2));
        float m0n = fmaxf(m0, tm0), m1n = fmaxf(m1, tm1);
        float c0 = exp2f((m0 - m0n) * SC), c1 = exp2f((m1 - m1n) * SC);

        const bool domask = (kt >= 2 * qt);
        float l0a = 0.f, l1a = 0.f;
        #pragma unroll
        for (int j = 0; j < 8; j++) {
            float p0 = exp2f((s[j][0] - m0n) * SC);
            float p1 = exp2f((s[j][1] - m0n) * SC);
            float p2 = exp2f((s[j][2] - m1n) * SC);
            float p3 = exp2f((s[j][3] - m1n) * SC);
            if (domask) {
                int colb = kt * 64 + j * 8 + 2 * (lane & 3);
                if (colb     > qg0) p0 = 0.f;
                if (colb + 1 > qg0) p1 = 0.f;
                if (colb     > qg1) p2 = 0.f;
                if (colb + 1 > qg1) p3 = 0.f;
            }
            s[j][0] = p0; s[j][1] = p1; s[j][2] = p2; s[j][3] = p3;
            l0a += p0 + p1; l1a += p2 + p3;
        }
        l0a += __shfl_xor_sync(0xffffffffu, l0a, 1);
        l0a += __shfl_xor_sync(0xffffffffu, l0a, 2);
        l1a += __shfl_xor_sync(0xffffffffu, l1a, 1);
        l1a += __shfl_xor_sync(0xffffffffu, l1a, 2);
        l0 = l0 * c0 + l0a;
        l1 = l1 * c1 + l1a;
        m0 = m0n; m1 = m1n;

        #pragma unroll
        for (int i = 0; i < 16; i++) {
            o[i][0] *= c0; o[i][1] *= c0; o[i][2] *= c1; o[i][3] *= c1;
        }

        #pragma unroll
        for (int ks = 0; ks < 4; ks++) {
            uint32_t ah[4], al[4];
            split_pair(s[2*ks][0],   s[2*ks][1],   ah[0], al[0]);
            split_pair(s[2*ks][2],   s[2*ks][3],   ah[1], al[1]);
            split_pair(s[2*ks+1][0], s[2*ks+1][1], ah[2], al[2]);
            split_pair(s[2*ks+1][2], s[2*ks+1][3], ah[3], al[3]);
            #pragma unroll
            for (int dp = 0; dp < 8; dp++) {
                uint32_t th[4], tl[4];
                uint32_t rb = stb + FVH_OFF
                            + (uint32_t)((ks * 16 + (lane & 15)) * 272)
                            + (uint32_t)((dp * 16 + ((lane >> 4) << 3)) * 2);
                ldsm_x4_t(th, rb);
                ldsm_x4_t(tl, rb + (FVL_OFF - FVH_OFF));
                uint32_t bh0[2] = {th[0], th[1]}, bh1[2] = {th[2], th[3]};
                uint32_t bl0[2] = {tl[0], tl[1]}, bl1[2] = {tl[2], tl[3]};
                mma_f16(o[2*dp],   ah, bh0);
                mma_f16(o[2*dp],   ah, bl0);
                mma_f16(o[2*dp],   al, bh0);
                mma_f16(o[2*dp+1], ah, bh1);
                mma_f16(o[2*dp+1], ah, bl1);
                mma_f16(o[2*dp+1], al, bh1);
            }
        }
        __syncthreads();
    }

    float inv0 = 1.f / l0, inv1 = 1.f / l1;
    const size_t tok0 = (size_t)(b * SEQ + qt * 128 + warp * 16 + (lane >> 2));
    #pragma unroll
    for (int dt = 0; dt < 16; dt++) {
        int col = hd * HDIM + dt * 8 + 2 * (lane & 3);
        uint32_t hu, lu;
        split_pair(o[dt][0] * inv0, o[dt][1] * inv0, hu, lu);
        *(uint32_t*)(Oh + tok0 * EMB + col) = hu;
        *(uint32_t*)(Ol + tok0 * EMB + col) = lu;
        split_pair(o[dt][2] * inv1, o[dt][3] * inv1, hu, lu);
        *(uint32_t*)(Oh + (tok0 + 8) * EMB + col) = hu;
        *(uint32_t*)(Ol + (tok0 + 8) * EMB + col) = lu;
    }
}

// ---------------------------------------------------------------------------
// out = rmsnorm(a + b) * w ; optional fp16 split outputs
// ---------------------------------------------------------------------------
__global__ __launch_bounds__(256) void add_rmsnorm_kernel(const float* __restrict__ a,
                                                          const float* __restrict__ b,
                                                          const float* __restrict__ w,
                                                          float* __restrict__ out,
                                                          f16* __restrict__ oh,
                                                          f16* __restrict__ ol) {
    int row = blockIdx.x;
    const float4* a4 = (const float4*)(a + (size_t)row * EMB);
    const float4* b4 = (const float4*)(b + (size_t)row * EMB);
    const float4* w4 = (const float4*)w;
    float4* o4 = (float4*)(out + (size_t)row * EMB);

    float4 s[2];
    float ss = 0.f;
    #pragma unroll
    for (int i = 0; i < 2; i++) {
        float4 av = a4[threadIdx.x + i * 256];
        float4 bv = b4[threadIdx.x + i * 256];
        s[i] = make_float4(av.x + bv.x, av.y + bv.y, av.z + bv.z, av.w + bv.w);
        ss += s[i].x * s[i].x + s[i].y * s[i].y + s[i].z * s[i].z + s[i].w * s[i].w;
    }
    __shared__ float red[8];
    for (int o = 16; o > 0; o >>= 1) ss += __shfl_xor_sync(0xffffffff, ss, o);
    if ((threadIdx.x & 31) == 0) red[threadIdx.x >> 5] = ss;
    __syncthreads();
    __shared__ float total_s;
    if (threadIdx.x == 0) {
        float t = 0.f;
        #pragma unroll
        for (int i = 0; i < 8; i++) t += red[i];
        total_s = t;
    }
    __syncthreads();
    float rstd = rsqrtf(total_s / (float)EMB + 1e-6f);
    #pragma unroll
    for (int i = 0; i < 2; i++) {
        float4 wv = w4[threadIdx.x + i * 256];
        float4 ov = make_float4(s[i].x * rstd * wv.x, s[i].y * rstd * wv.y,
                                s[i].z * rstd * wv.z, s[i].w * rstd * wv.w);
        o4[threadIdx.x + i * 256] = ov;
        if (oh) {
            size_t base = (size_t)row * EMB + (threadIdx.x + i * 256) * 4;
            uint32_t hu, lu;
            split_pair(ov.x, ov.y, hu, lu);
            *(uint32_t*)(oh + base) = hu; *(uint32_t*)(ol + base) = lu;
            split_pair(ov.z, ov.w, hu, lu);
            *(uint32_t*)(oh + base + 2) = hu; *(uint32_t*)(ol + base + 2) = lu;
        }
    }
}

// ---------------------------------------------------------------------------
// Launch
// ---------------------------------------------------------------------------
extern "C" void kernel_launch(void* const* d_in, const int* in_sizes, int n_in,
                              void* d_out, int out_size) {
    const float* x       = (const float*)d_in[0];
    const float* wq      = (const float*)d_in[1];
    const float* wk      = (const float*)d_in[2];
    const float* wv      = (const float*)d_in[3];
    const float* wo      = (const float*)d_in[4];
    const float* norm1_w = (const float*)d_in[5];
    const float* norm2_w = (const float*)d_in[6];
    const float* w_in    = (const float*)d_in[7];
    const float* w_out   = (const float*)d_in[8];
    float* out = (float*)d_out;

    f16 *xrh, *xrl, *xh, *xl, *qh, *ql, *kh, *kl, *vh, *vl, *ctxh, *ctxl;
    f16 *hh, *hl, *acth, *actl;
    f16 *wqT, *wkT, *wvT, *woT, *winT, *woutT;
    float *attn, *h, *fc;
    cudaGetSymbolAddress((void**)&xrh,  g_xrot_hi);
    cudaGetSymbolAddress((void**)&xrl,  g_xrot_lo);
    cudaGetSymbolAddress((void**)&xh,   g_x_hi);
    cudaGetSymbolAddress((void**)&xl,   g_x_lo);
    cudaGetSymbolAddress((void**)&qh,   g_q_hi);
    cudaGetSymbolAddress((void**)&ql,   g_q_lo);
    cudaGetSymbolAddress((void**)&kh,   g_k_hi);
    cudaGetSymbolAddress((void**)&kl,   g_k_lo);
    cudaGetSymbolAddress((void**)&vh,   g_v_hi);
    cudaGetSymbolAddress((void**)&vl,   g_v_lo);
    cudaGetSymbolAddress((void**)&ctxh, g_ctx_hi);
    cudaGetSymbolAddress((void**)&ctxl, g_ctx_lo);
    cudaGetSymbolAddress((void**)&attn, g_attn);
    cudaGetSymbolAddress((void**)&h,    g_h);
    cudaGetSymbolAddress((void**)&hh,   g_h_hi);
    cudaGetSymbolAddress((void**)&hl,   g_h_lo);
    cudaGetSymbolAddress((void**)&acth, g_act_hi);
    cudaGetSymbolAddress((void**)&actl, g_act_lo);
    cudaGetSymbolAddress((void**)&fc,   g_fc);
    cudaGetSymbolAddress((void**)&wqT,  g_wqT);
    cudaGetSymbolAddress((void**)&wkT,  g_wkT);
    cudaGetSymbolAddress((void**)&wvT,  g_wvT);
    cudaGetSymbolAddress((void**)&woT,  g_woT);
    cudaGetSymbolAddress((void**)&winT, g_winT);
    cudaGetSymbolAddress((void**)&woutT,g_woutT);

    cudaFuncSetAttribute(mma_gemm, cudaFuncAttributeMaxDynamicSharedMemorySize,
                         MG_SMEM);
    cudaFuncSetAttribute(flash_mma_kernel, cudaFuncAttributeMaxDynamicSharedMemorySize,
                         FL_SMEM);

    // 0. Transpose weights -> [N][K] fp16 hi (w_in rows interleaved a/g)
    transpose_h_kernel<<<dim3(EMB/32,   EMB/32), 256>>>(wq,    wqT,   EMB, EMB, 0);
    transpose_h_kernel<<<dim3(KVW/32,   EMB/32), 256>>>(wk,    wkT,   EMB, KVW, 0);
    transpose_h_kernel<<<dim3(KVW/32,   EMB/32), 256>>>(wv,    wvT,   EMB, KVW, 0);
    transpose_h_kernel<<<dim3(EMB/32,   EMB/32), 256>>>(wo,    woT,   EMB, EMB, 0);
    transpose_h_kernel<<<dim3(2*FFN/32, EMB/32), 256>>>(w_in,  winT,  EMB, 2*FFN, FFN);
    transpose_h_kernel<<<dim3(EMB/32,   FFN/32), 256>>>(w_out, woutT, FFN, EMB, 0);

    // 1. RoPE (+split) and split(x)
    rope_split_kernel<<<(TOK * EMB + 255) / 256, 256>>>(x, xrh, xrl);
    split_kernel<<<(TOK * EMB + 255) / 256, 256>>>(x, xh, xl, (size_t)TOK * EMB);

    // 2-4. Q/K/V projections -> fp16 hi/lo outputs
    mma_gemm<<<dim3(TOK/128, EMB/128), 256, MG_SMEM>>>(xrh, xrl, wqT,
        nullptr, qh, ql, TOK, EMB, EMB, 1);
    mma_gemm<<<dim3(TOK/128, KVW/128), 256, MG_SMEM>>>(xrh, xrl, wkT,
        nullptr, kh, kl, TOK, KVW, EMB, 1);
    mma_gemm<<<dim3(TOK/128, KVW/128), 256, MG_SMEM>>>(xh,  xl,  wvT,
        nullptr, vh, vl, TOK, KVW, EMB, 1);

    // 5. Flash attention -> ctx hi/lo (full 3-term fp16)
    flash_mma_kernel<<<dim3(SEQ/128, NHEAD, BATCH), 256, FL_SMEM>>>(
        qh, ql, kh, kl, vh, vl, ctxh, ctxl);

    // 6. Output projection (fp32 out)
    mma_gemm<<<dim3(TOK/128, EMB/128), 256, MG_SMEM>>>(ctxh, ctxl, woT,
        attn, nullptr, nullptr, TOK, EMB, EMB, 0);

    // 7. h = rmsnorm(x + attn) * norm1_w  (+ fp16 split)
    add_rmsnorm_kernel<<<TOK, 256>>>(x, attn, norm1_w, h, hh, hl);

    // 8+9. act = geglu(h @ w_in) fused (w_in rows interleaved a/g)
    mma_gemm<<<dim3(TOK/128, 2*FFN/128), 256, MG_SMEM>>>(hh, hl, winT,
        nullptr, acth, actl, TOK, 2*FFN, EMB, 2);

    // 10. fc = act @ w_out (fp32 out)
    mma_gemm<<<dim3(TOK/128, EMB/128), 256, MG_SMEM>>>(acth, actl, woutT,
        fc, nullptr, nullptr, TOK, EMB, FFN, 0);

    // 11. out = rmsnorm(h + fc) * norm2_w
    add_rmsnorm_kernel<<<TOK, 256>>>(h, fc, norm2_w, out, nullptr, nullptr);
}

// round 16
// speedup vs baseline: 4.5724x; 1.6316x over previous
#include <cuda_runtime.h>
#include <cuda_fp16.h>
#include <math.h>
#include <stdint.h>

// Problem constants
#define BATCH 2
#define SEQ   2048
#define EMB   2048
#define NHEAD 16
#define NGRP  4
#define HDIM  128
#define FFN   8192
#define TOK   (BATCH*SEQ)          // 4096 rows
#define KVW   (NGRP*HDIM)          // 512

typedef __half f16;

// ---------------------------------------------------------------------------
// PTX helpers (portable sm_80+: cp.async / ldmatrix / mma.sync)
// ---------------------------------------------------------------------------
__device__ __forceinline__ uint32_t smem_to_u32(const void* smem_ptr) {
    uint32_t addr;
    asm("{ .reg .u64 tmp; cvta.to.shared.u64 tmp, %1; cvt.u32.u64 %0, tmp; }"
        : "=r"(addr) : "l"(smem_ptr));
    return addr;
}

#define CP_ASYNC16(dst, src) \
    asm volatile("cp.async.cg.shared.global [%0], [%1], 16;\n" \
                 :: "r"(dst), "l"(src))
#define CP_COMMIT() asm volatile("cp.async.commit_group;\n" ::: "memory")
#define CP_WAIT(N)  asm volatile("cp.async.wait_group %0;\n" :: "n"(N) : "memory")

__device__ __forceinline__ void ldsm_x4(uint32_t* r, uint32_t addr) {
    asm volatile("ldmatrix.sync.aligned.m8n8.x4.shared.b16 {%0,%1,%2,%3}, [%4];\n"
        : "=r"(r[0]), "=r"(r[1]), "=r"(r[2]), "=r"(r[3]) : "r"(addr));
}

__device__ __forceinline__ void ldsm_x4_t(uint32_t* r, uint32_t addr) {
    asm volatile("ldmatrix.sync.aligned.m8n8.x4.trans.shared.b16 {%0,%1,%2,%3}, [%4];\n"
        : "=r"(r[0]), "=r"(r[1]), "=r"(r[2]), "=r"(r[3]) : "r"(addr));
}

__device__ __forceinline__ void mma_f16(float* c, const uint32_t* a, const uint32_t* b) {
    asm volatile(
        "mma.sync.aligned.m16n8k16.row.col.f32.f16.f16.f32 "
        "{%0,%1,%2,%3}, {%4,%5,%6,%7}, {%8,%9}, {%0,%1,%2,%3};\n"
        : "+f"(c[0]), "+f"(c[1]), "+f"(c[2]), "+f"(c[3])
        : "r"(a[0]), "r"(a[1]), "r"(a[2]), "r"(a[3]), "r"(b[0]), "r"(b[1]));
}

// pack float pair -> f16x2 as uint32
__device__ __forceinline__ uint32_t pack_h2(float a, float b) {
    __half2 h = __float22half2_rn(make_float2(a, b));
    return *reinterpret_cast<uint32_t*>(&h);
}

// pack float pair -> (hi f16x2, lo f16x2) as uint32 (used for P split in flash)
__device__ __forceinline__ void split_pair(float a, float b, uint32_t& hu, uint32_t& lu) {
    __half2 h = __float22half2_rn(make_float2(a, b));
    float2 back = __half22float2(h);
    __half2 l = __float22half2_rn(make_float2(a - back.x, b - back.y));
    hu = *reinterpret_cast<uint32_t*>(&h);
    lu = *reinterpret_cast<uint32_t*>(&l);
}

__device__ __forceinline__ float gelu_exact(float a) {
    return 0.5f * a * (1.0f + erff(a * 0.70710678118654752f));
}

// ---------------------------------------------------------------------------
// Scratch (device globals; allocation-free per harness rules)
// ---------------------------------------------------------------------------
__device__ __align__(256) f16 g_xrot[TOK*EMB];
__device__ __align__(256) f16 g_xf[TOK*EMB];
__device__ __align__(256) f16 g_q[TOK*EMB];
__device__ __align__(256) f16 g_k[TOK*KVW];
__device__ __align__(256) f16 g_v[TOK*KVW];
__device__ __align__(256) f16 g_ctx[TOK*EMB];
__device__ __align__(256) float g_attn[TOK*EMB];
__device__ __align__(256) float g_h[TOK*EMB];
__device__ __align__(256) f16 g_h16[TOK*EMB];
__device__ __align__(256) f16 g_act[(size_t)TOK*FFN];
__device__ __align__(256) float g_fc[TOK*EMB];
// transposed weights, fp16 (B-side of all GEMMs)
__device__ __align__(256) f16 g_wqT[EMB*EMB];
__device__ __align__(256) f16 g_wkT[KVW*EMB];
__device__ __align__(256) f16 g_wvT[KVW*EMB];
__device__ __align__(256) f16 g_woT[EMB*EMB];
__device__ __align__(256) f16 g_winT[(size_t)2*FFN*EMB];
__device__ __align__(256) f16 g_woutT[(size_t)EMB*FFN];

// ---------------------------------------------------------------------------
// Transpose -> fp16; optional row-interleave for GeGLU pairing
// ---------------------------------------------------------------------------
__global__ __launch_bounds__(256) void transpose_h_kernel(
        const float* __restrict__ in, f16* __restrict__ hi,
        int R, int C, int ilv_half) {
    __shared__ float t[32][33];
    int bx = blockIdx.x * 32, by = blockIdx.y * 32;
    int tx = threadIdx.x & 31, ty = threadIdx.x >> 5;
    #pragma unroll
    for (int i = ty; i < 32; i += 8)
        t[i][tx] = in[(size_t)(by + i) * C + bx + tx];
    __syncthreads();
    #pragma unroll
    for (int i = ty; i < 32; i += 8) {
        float v = t[tx][i];
        size_t r = (size_t)(bx + i);
        if (ilv_half) r = (r < (size_t)ilv_half) ? 2*r : 2*(r - ilv_half) + 1;
        hi[r * R + by + tx] = __float2half_rn(v);
    }
}

__global__ __launch_bounds__(256) void cvt_kernel(const float* __restrict__ in,
                                                  f16* __restrict__ o, size_t n) {
    size_t idx = ((size_t)blockIdx.x * 256 + threadIdx.x) * 4;
    if (idx >= n) return;
    float4 v = *(const float4*)(in + idx);
    uint32_t p0 = pack_h2(v.x, v.y), p1 = pack_h2(v.z, v.w);
    *(uint32_t*)(o + idx) = p0;
    *(uint32_t*)(o + idx + 2) = p1;
}

// ---------------------------------------------------------------------------
// RoPE -> fp16
// ---------------------------------------------------------------------------
__global__ __launch_bounds__(256) void rope_kernel(const float* __restrict__ x,
                                                   f16* __restrict__ o) {
    int idx = blockIdx.x * 256 + threadIdx.x;
    if (idx >= TOK*EMB) return;
    int t = idx / EMB;
    int e = idx % EMB;
    int n = t % SEQ;
    int d = e % HDIM;
    int j; float partner; float sign;
    if (d < 64) { j = d;      partner = x[idx + 64]; sign = -1.f; }
    else        { j = d - 64; partner = x[idx - 64]; sign =  1.f; }
    float invf = powf(10000.0f, -(float)j / 64.0f);
    float ang = (float)n * invf;
    float c = cosf(ang), s = sinf(ang);
    o[idx] = __float2half_rn(x[idx] * c + sign * partner * s);
}

// ---------------------------------------------------------------------------
// Pure fp16 tensor-core GEMM: C = A @ B^T (1 HMMA per position).
// 128x128 tile, Kstep 32, 8 warps, 2-stage cp.async, 2 CTAs/SM.
// mode: 0 = fp32 C; 1 = f16 C; 2 = GeGLU epilogue -> f16 act width N/2.
// ---------------------------------------------------------------------------
#define WST_B    80
#define OP_BYTES (128*WST_B)
#define STAGE_B  (2*OP_BYTES)    // 20480 (A, B)
#define MG_SMEM  (2*STAGE_B)     // 40960 per CTA

__global__ __launch_bounds__(256, 2) void mma_gemm(
        const f16* __restrict__ A, const f16* __restrict__ B,
        float* __restrict__ C, f16* __restrict__ Ch,
        int M, int N, int K, int mode) {
    extern __shared__ char smem[];
    const uint32_t sb = smem_to_u32(smem);
    const int tid = threadIdx.x;
    const int m0 = blockIdx.x * 128, n0 = blockIdx.y * 128;
    const int warp = tid >> 5, lane = tid & 31;
    const int wm = warp & 1, wn = warp >> 1;

    const f16* srcs[2] = { A + (size_t)m0 * K, B + (size_t)n0 * K };

    float acc[4][4][4];
    #pragma unroll
    for (int i = 0; i < 4; i++)
        #pragma unroll
        for (int j = 0; j < 4; j++)
            #pragma unroll
            for (int r = 0; r < 4; r++) acc[i][j][r] = 0.f;

    const int S = K >> 5;
    const int lA_row = lane & 15, lA_k = lane >> 4;
    const int lB_row = ((lane >> 4) << 3) + (lane & 7);
    const int lB_k = (lane >> 3) & 1;

    auto issue_stage = [&](int s) {
        const uint32_t bufb = sb + (uint32_t)(s & 1) * STAGE_B;
        const int k0 = s << 5;
        #pragma unroll
        for (int it = 0; it < 4; it++) {
            int idx = tid + (it << 8);       // 0..1023
            int op = idx >> 9;               // 0=A,1=B
            int j = idx & 511;
            int row = j >> 2, ch = j & 3;
            const f16* src = srcs[op] + (size_t)row * K + k0 + ch * 8;
            uint32_t dst = bufb + (uint32_t)(op * OP_BYTES + row * WST_B + ch * 16);
            CP_ASYNC16(dst, src);
        }
    };

    issue_stage(0); CP_COMMIT();

    for (int s = 0; s < S; s++) {
        if (s + 1 < S) {
            issue_stage(s + 1);
            CP_COMMIT();
            CP_WAIT(1);
        } else {
            CP_WAIT(0);
        }
        __syncthreads();

        const uint32_t base = sb + (uint32_t)(s & 1) * STAGE_B;
        #pragma unroll
        for (int k16 = 0; k16 < 2; k16++) {
            uint32_t bh[4][2];
            #pragma unroll
            for (int np = 0; np < 2; np++) {
                uint32_t rb = base + OP_BYTES
                            + (uint32_t)((wn * 32 + np * 16 + lB_row) * WST_B)
                            + k16 * 32 + lB_k * 16;
                uint32_t t4[4];
                ldsm_x4(t4, rb);
                bh[np*2][0] = t4[0]; bh[np*2][1] = t4[1];
                bh[np*2+1][0] = t4[2]; bh[np*2+1][1] = t4[3];
            }
            #pragma unroll
            for (int mt = 0; mt < 4; mt++) {
                uint32_t ah[4];
                uint32_t ra = base + (uint32_t)((wm * 64 + mt * 16 + lA_row) * WST_B)
                            + k16 * 32 + lA_k * 16;
                ldsm_x4(ah, ra);
                #pragma unroll
                for (int nt = 0; nt < 4; nt++)
                    mma_f16(acc[mt][nt], ah, bh[nt]);
            }
        }
        __syncthreads();
    }

    #pragma unroll
    for (int mt = 0; mt < 4; mt++) {
        int m = m0 + wm * 64 + mt * 16 + (lane >> 2);
        #pragma unroll
        for (int nt = 0; nt < 4; nt++) {
            int n = n0 + wn * 32 + nt * 8 + 2 * (lane & 3);
            if (mode == 0) {
                *(float2*)(C + (size_t)m * N + n) =
                    make_float2(acc[mt][nt][0], acc[mt][nt][1]);
                *(float2*)(C + (size_t)(m + 8) * N + n) =
                    make_float2(acc[mt][nt][2], acc[mt][nt][3]);
            } else if (mode == 1) {
                *(uint32_t*)(Ch + (size_t)m * N + n) =
                    pack_h2(acc[mt][nt][0], acc[mt][nt][1]);
                *(uint32_t*)(Ch + (size_t)(m + 8) * N + n) =
                    pack_h2(acc[mt][nt][2], acc[mt][nt][3]);
            } else {
                // GeGLU: (c0,c1)=(a,g) for row m; (c2,c3) for row m+8
                int Nh = N >> 1;
                int f = n >> 1;
                float v0 = gelu_exact(acc[mt][nt][0]) * acc[mt][nt][1];
                float v1 = gelu_exact(acc[mt][nt][2]) * acc[mt][nt][3];
                Ch[(size_t)m * Nh + f] = __float2half_rn(v0);
                Ch[(size_t)(m + 8) * Nh + f] = __float2half_rn(v1);
            }
        }
    }
}

// ---------------------------------------------------------------------------
// Tensor-core flash attention (fp16, causal, GQA).
// QK^T: single fp16 MMA per fragment (fp16 products exact in fp32 accum).
// P@V:  P split 2-term in registers x single-V.
// Q [128][272B] resident; K,V [64][272B] per-stage, 2-stage cp.async ring.
// ---------------------------------------------------------------------------
#define FSQ    0
#define FST0   34816
#define FSTAGE 34816          // per-stage: KH, VH each 64*272=17408
#define FV_OFF 17408
#define FL_SMEM (FST0 + 2*FSTAGE)   // 104448

__global__ __launch_bounds__(256) void flash_mma_kernel(
        const f16* __restrict__ Q, const f16* __restrict__ K,
        const f16* __restrict__ V, f16* __restrict__ O) {
    extern __shared__ char smem[];
    const uint32_t sb = smem_to_u32(smem);
    const int qt = (int)gridDim.x - 1 - (int)blockIdx.x;  // big tiles first
    const int hd = blockIdx.y, b = blockIdx.z;
    const int g = hd / (NHEAD / NGRP);
    const int tid = threadIdx.x;
    const int warp = tid >> 5, lane = tid & 31;
    const int lA_row = lane & 15, lA_k = lane >> 4;
    const int lB_row = ((lane >> 4) << 3) + (lane & 7);
    const int lB_k = (lane >> 3) & 1;
    const float SC = 0.08838834764831845f * 1.4426950408889634f;  // scale*log2e

    // load Q tile (128 x 128 f16)
    {
        const size_t qbase = ((size_t)(b * SEQ + qt * 128)) * EMB + hd * HDIM;
        #pragma unroll
        for (int it = 0; it < 8; it++) {
            int i = tid + (it << 8);       // 0..2047
            int row = i >> 4, ch = i & 15;
            size_t ga = qbase + (size_t)row * EMB + ch * 8;
            *(uint4*)(smem + FSQ + row * 272 + ch * 16) = *(const uint4*)(Q + ga);
        }
    }

    auto issue_kv = [&](int kt) {
        const uint32_t stb = sb + FST0 + (uint32_t)(kt & 1) * FSTAGE;
        const size_t kbase = ((size_t)(b * SEQ + kt * 64)) * KVW + g * HDIM;
        #pragma unroll
        for (int it = 0; it < 8; it++) {
            int idx = tid + (it << 8);     // 0..2047
            int arr = idx >> 10;           // 0=K,1=V
            int j = idx & 1023;
            int row = j >> 4, ch = j & 15;
            const f16* src = (arr ? V : K) + kbase + (size_t)row * KVW + ch * 8;
            uint32_t dst = stb + (uint32_t)arr * (uint32_t)FV_OFF
                         + (uint32_t)(row * 272 + ch * 16);
            CP_ASYNC16(dst, src);
        }
    };

    float o[16][4];
    #pragma unroll
    for (int i = 0; i < 16; i++)
        #pragma unroll
        for (int r = 0; r < 4; r++) o[i][r] = 0.f;
    float m0 = -1e30f, m1 = -1e30f, l0 = 0.f, l1 = 0.f;

    const int qg0 = qt * 128 + warp * 16 + (lane >> 2);
    const int qg1 = qg0 + 8;
    const int NT = 2 * qt + 2;

    issue_kv(0);
    CP_COMMIT();

    for (int kt = 0; kt < NT; kt++) {
        if (kt + 1 < NT) {
            issue_kv(kt + 1);
            CP_COMMIT();
            CP_WAIT(1);
        } else {
            CP_WAIT(0);
        }
        __syncthreads();
        const uint32_t stb = sb + FST0 + (uint32_t)(kt & 1) * FSTAGE;

        // --- S = Q @ K^T (single fp16 MMA per fragment) ---
        float s[8][4];
        #pragma unroll
        for (int j = 0; j < 8; j++)
            #pragma unroll
            for (int r = 0; r < 4; r++) s[j][r] = 0.f;

        #pragma unroll
        for (int ks = 0; ks < 8; ks++) {
            uint32_t q4[4];
            uint32_t ra = sb + FSQ + (uint32_t)((warp * 16 + lA_row) * 272)
                        + ks * 32 + lA_k * 16;
            ldsm_x4(q4, ra);
            #pragma unroll
            for (int np = 0; np < 4; np++) {
                uint32_t th[4];
                uint32_t rb = stb + (uint32_t)((np * 16 + lB_row) * 272)
                            + ks * 32 + lB_k * 16;
                ldsm_x4(th, rb);
                uint32_t bh0[2] = {th[0], th[1]}, bh1[2] = {th[2], th[3]};
                mma_f16(s[2*np],   q4, bh0);
                mma_f16(s[2*np+1], q4, bh1);
            }
        }

        // --- online softmax (raw-score max; mask by zeroing p) ---
        float tm0 = -1e30f, tm1 = -1e30f;
        #pragma unroll
        for (int j = 0; j < 8; j++) {
            tm0 = fmaxf(tm0, fmaxf(s[j][0], s[j][1]));
            tm1 = fmaxf(tm1, fmaxf(s[j][2], s[j][3]));
        }
        tm0 = fmaxf(tm0, __shfl_xor_sync(0xffffffffu, tm0, 1));
        tm0 = fmaxf(tm0, __shfl_xor_sync(0xffffffffu, tm0, 2));
        tm1 = fmaxf(tm1, __shfl_xor_sync(0xffffffffu, tm1, 1));
        tm1 = fmaxf(tm1, __shfl_xor_sync(0xffffffffu, tm1, 2));
        float m0n = fmaxf(m0, tm0), m1n = fmaxf(m1, tm1);
        float c0 = exp2f((m0 - m0n) * SC), c1 = exp2f((m1 - m1n) * SC);

        const bool domask = (kt >= 2 * qt);
        float l0a = 0.f, l1a = 0.f;
        #pragma unroll
        for (int j = 0; j < 8; j++) {
            float p0 = exp2f((s[j][0] - m0n) * SC);
            float p1 = exp2f((s[j][1] - m0n) * SC);
            float p2 = exp2f((s[j][2] - m1n) * SC);
            float p3 = exp2f((s[j][3] - m1n) * SC);
            if (domask) {
                int colb = kt * 64 + j * 8 + 2 * (lane & 3);
                if (colb     > qg0) p0 = 0.f;
                if (colb + 1 > qg0) p1 = 0.f;
                if (colb     > qg1) p2 = 0.f;
                if (colb + 1 > qg1) p3 = 0.f;
            }
            s[j][0] = p0; s[j][1] = p1; s[j][2] = p2; s[j][3] = p3;
            l0a += p0 + p1; l1a += p2 + p3;
        }
        l0a += __shfl_xor_sync(0xffffffffu, l0a, 1);
        l0a += __shfl_xor_sync(0xffffffffu, l0a, 2);
        l1a += __shfl_xor_sync(0xffffffffu, l1a, 1);
        l1a += __shfl_xor_sync(0xffffffffu, l1a, 2);
        l0 = l0 * c0 + l0a;
        l1 = l1 * c1 + l1a;
        m0 = m0n; m1 = m1n;

        #pragma unroll
        for (int i = 0; i < 16; i++) {
            o[i][0] *= c0; o[i][1] *= c0; o[i][2] *= c1; o[i][3] *= c1;
        }

        // --- O += P @ V (P 2-term x single V; V [kv][d] via ldmatrix.trans) ---
        #pragma unroll
        for (int ks = 0; ks < 4; ks++) {
            uint32_t ah[4], al[4];
            split_pair(s[2*ks][0],   s[2*ks][1],   ah[0], al[0]);
            split_pair(s[2*ks][2],   s[2*ks][3],   ah[1], al[1]);
            split_pair(s[2*ks+1][0], s[2*ks+1][1], ah[2], al[2]);
            split_pair(s[2*ks+1][2], s[2*ks+1][3], ah[3], al[3]);
            #pragma unroll
            for (int dp = 0; dp < 8; dp++) {
                uint32_t th[4];
                uint32_t rb = stb + FV_OFF
                            + (uint32_t)((ks * 16 + (lane & 15)) * 272)
                            + (uint32_t)((dp * 16 + ((lane >> 4) << 3)) * 2);
                ldsm_x4_t(th, rb);
                uint32_t bh0[2] = {th[0], th[1]}, bh1[2] = {th[2], th[3]};
                mma_f16(o[2*dp],   ah, bh0);
                mma_f16(o[2*dp],   al, bh0);
                mma_f16(o[2*dp+1], ah, bh1);
                mma_f16(o[2*dp+1], al, bh1);
            }
        }
        __syncthreads();   // all warps done reading stage kt&1 before overwrite
    }

    // epilogue: divide by l, write ctx f16
    float inv0 = 1.f / l0, inv1 = 1.f / l1;
    const size_t tok0 = (size_t)(b * SEQ + qt * 128 + warp * 16 + (lane >> 2));
    #pragma unroll
    for (int dt = 0; dt < 16; dt++) {
        int col = hd * HDIM + dt * 8 + 2 * (lane & 3);
        *(uint32_t*)(O + tok0 * EMB + col) =
            pack_h2(o[dt][0] * inv0, o[dt][1] * inv0);
        *(uint32_t*)(O + (tok0 + 8) * EMB + col) =
            pack_h2(o[dt][2] * inv1, o[dt][3] * inv1);
    }
}

// ---------------------------------------------------------------------------
// out = rmsnorm(a + b) * w ; optional f16 output
// ---------------------------------------------------------------------------
__global__ __launch_bounds__(256) void add_rmsnorm_kernel(const float* __restrict__ a,
                                                          const float* __restrict__ b,
                                                          const float* __restrict__ w,
                                                          float* __restrict__ out,
                                                          f16* __restrict__ oh) {
    int row = blockIdx.x;
    const float4* a4 = (const float4*)(a + (size_t)row * EMB);
    const float4* b4 = (const float4*)(b + (size_t)row * EMB);
    const float4* w4 = (const float4*)w;
    float4* o4 = (float4*)(out + (size_t)row * EMB);

    float4 s[2];
    float ss = 0.f;
    #pragma unroll
    for (int i = 0; i < 2; i++) {
        float4 av = a4[threadIdx.x + i * 256];
        float4 bv = b4[threadIdx.x + i * 256];
        s[i] = make_float4(av.x + bv.x, av.y + bv.y, av.z + bv.z, av.w + bv.w);
        ss += s[i].x * s[i].x + s[i].y * s[i].y + s[i].z * s[i].z + s[i].w * s[i].w;
    }
    __shared__ float red[8];
    for (int o = 16; o > 0; o >>= 1) ss += __shfl_xor_sync(0xffffffff, ss, o);
    if ((threadIdx.x & 31) == 0) red[threadIdx.x >> 5] = ss;
    __syncthreads();
    __shared__ float total_s;
    if (threadIdx.x == 0) {
        float t = 0.f;
        #pragma unroll
        for (int i = 0; i < 8; i++) t += red[i];
        total_s = t;
    }
    __syncthreads();
    float rstd = rsqrtf(total_s / (float)EMB + 1e-6f);
    #pragma unroll
    for (int i = 0; i < 2; i++) {
        float4 wv = w4[threadIdx.x + i * 256];
        float4 ov = make_float4(s[i].x * rstd * wv.x, s[i].y * rstd * wv.y,
                                s[i].z * rstd * wv.z, s[i].w * rstd * wv.w);
        o4[threadIdx.x + i * 256] = ov;
        if (oh) {
            size_t base = (size_t)row * EMB + (threadIdx.x + i * 256) * 4;
            *(uint32_t*)(oh + base)     = pack_h2(ov.x, ov.y);
            *(uint32_t*)(oh + base + 2) = pack_h2(ov.z, ov.w);
        }
    }
}

// ---------------------------------------------------------------------------
// Launch
// ---------------------------------------------------------------------------
extern "C" void kernel_launch(void* const* d_in, const int* in_sizes, int n_in,
                              void* d_out, int out_size) {
    const float* x       = (const float*)d_in[0];
    const float* wq      = (const float*)d_in[1];
    const float* wk      = (const float*)d_in[2];
    const float* wv      = (const float*)d_in[3];
    const float* wo      = (const float*)d_in[4];
    const float* norm1_w = (const float*)d_in[5];
    const float* norm2_w = (const float*)d_in[6];
    const float* w_in    = (const float*)d_in[7];
    const float* w_out   = (const float*)d_in[8];
    float* out = (float*)d_out;

    f16 *xrot, *xf, *q, *k, *v, *ctx, *h16, *act;
    f16 *wqT, *wkT, *wvT, *woT, *winT, *woutT;
    float *attn, *h, *fc;
    cudaGetSymbolAddress((void**)&xrot, g_xrot);
    cudaGetSymbolAddress((void**)&xf,   g_xf);
    cudaGetSymbolAddress((void**)&q,    g_q);
    cudaGetSymbolAddress((void**)&k,    g_k);
    cudaGetSymbolAddress((void**)&v,    g_v);
    cudaGetSymbolAddress((void**)&ctx,  g_ctx);
    cudaGetSymbolAddress((void**)&attn, g_attn);
    cudaGetSymbolAddress((void**)&h,    g_h);
    cudaGetSymbolAddress((void**)&h16,  g_h16);
    cudaGetSymbolAddress((void**)&act,  g_act);
    cudaGetSymbolAddress((void**)&fc,   g_fc);
    cudaGetSymbolAddress((void**)&wqT,  g_wqT);
    cudaGetSymbolAddress((void**)&wkT,  g_wkT);
    cudaGetSymbolAddress((void**)&wvT,  g_wvT);
    cudaGetSymbolAddress((void**)&woT,  g_woT);
    cudaGetSymbolAddress((void**)&winT, g_winT);
    cudaGetSymbolAddress((void**)&woutT,g_woutT);

    cudaFuncSetAttribute(mma_gemm, cudaFuncAttributeMaxDynamicSharedMemorySize,
                         MG_SMEM);
    cudaFuncSetAttribute(flash_mma_kernel, cudaFuncAttributeMaxDynamicSharedMemorySize,
                         FL_SMEM);

    // 0. Transpose weights -> [N][K] fp16 (w_in rows interleaved a/g)
    transpose_h_kernel<<<dim3(EMB/32,   EMB/32), 256>>>(wq,    wqT,   EMB, EMB, 0);
    transpose_h_kernel<<<dim3(KVW/32,   EMB/32), 256>>>(wk,    wkT,   EMB, KVW, 0);
    transpose_h_kernel<<<dim3(KVW/32,   EMB/32), 256>>>(wv,    wvT,   EMB, KVW, 0);
    transpose_h_kernel<<<dim3(EMB/32,   EMB/32), 256>>>(wo,    woT,   EMB, EMB, 0);
    transpose_h_kernel<<<dim3(2*FFN/32, EMB/32), 256>>>(w_in,  winT,  EMB, 2*FFN, FFN);
    transpose_h_kernel<<<dim3(EMB/32,   FFN/32), 256>>>(w_out, woutT, FFN, EMB, 0);

    // 1. RoPE and cvt(x)
    rope_kernel<<<(TOK * EMB + 255) / 256, 256>>>(x, xrot);
    cvt_kernel<<<(TOK * EMB / 4 + 255) / 256, 256>>>(x, xf, (size_t)TOK * EMB);

    // 2-4. Q/K/V projections -> f16
    mma_gemm<<<dim3(TOK/128, EMB/128), 256, MG_SMEM>>>(xrot, wqT,
        nullptr, q, TOK, EMB, EMB, 1);
    mma_gemm<<<dim3(TOK/128, KVW/128), 256, MG_SMEM>>>(xrot, wkT,
        nullptr, k, TOK, KVW, EMB, 1);
    mma_gemm<<<dim3(TOK/128, KVW/128), 256, MG_SMEM>>>(xf,   wvT,
        nullptr, v, TOK, KVW, EMB, 1);

    // 5. Flash attention -> ctx f16
    flash_mma_kernel<<<dim3(SEQ/128, NHEAD, BATCH), 256, FL_SMEM>>>(q, k, v, ctx);

    // 6. Output projection (fp32 out)
    mma_gemm<<<dim3(TOK/128, EMB/128), 256, MG_SMEM>>>(ctx, woT,
        attn, nullptr, TOK, EMB, EMB, 0);

    // 7. h = rmsnorm(x + attn) * norm1_w (+ f16 copy)
    add_rmsnorm_kernel<<<TOK, 256>>>(x, attn, norm1_w, h, h16);

    // 8+9. act = geglu(h @ w_in) fused (w_in rows interleaved a/g)
    mma_gemm<<<dim3(TOK/128, 2*FFN/128), 256, MG_SMEM>>>(h16, winT,
        nullptr, act, TOK, 2*FFN, EMB, 2);

    // 10. fc = act @ w_out (fp32 out)
    mma_gemm<<<dim3(TOK/128, EMB/128), 256, MG_SMEM>>>(act, woutT,
        fc, nullptr, TOK, EMB, FFN, 0);

    // 11. out = rmsnorm(h + fc) * norm2_w
    add_rmsnorm_kernel<<<TOK, 256>>>(h, fc, norm2_w, out, nullptr);
}

// round 17
// speedup vs baseline: 5.1761x; 1.1320x over previous
#include <cuda_runtime.h>
#include <cuda_fp16.h>
#include <math.h>
#include <stdint.h>

// Problem constants
#define BATCH 2
#define SEQ   2048
#define EMB   2048
#define NHEAD 16
#define NGRP  4
#define HDIM  128
#define FFN   8192
#define TOK   (BATCH*SEQ)          // 4096 rows
#define KVW   (NGRP*HDIM)          // 512

typedef __half f16;

// ---------------------------------------------------------------------------
// PTX helpers (portable sm_80+: cp.async / ldmatrix / mma.sync)
// ---------------------------------------------------------------------------
__device__ __forceinline__ uint32_t smem_to_u32(const void* smem_ptr) {
    uint32_t addr;
    asm("{ .reg .u64 tmp; cvta.to.shared.u64 tmp, %1; cvt.u32.u64 %0, tmp; }"
        : "=r"(addr) : "l"(smem_ptr));
    return addr;
}

#define CP_ASYNC16(dst, src) \
    asm volatile("cp.async.cg.shared.global [%0], [%1], 16;\n" \
                 :: "r"(dst), "l"(src))
#define CP_COMMIT() asm volatile("cp.async.commit_group;\n" ::: "memory")
#define CP_WAIT(N)  asm volatile("cp.async.wait_group %0;\n" :: "n"(N) : "memory")

__device__ __forceinline__ void ldsm_x4(uint32_t* r, uint32_t addr) {
    asm volatile("ldmatrix.sync.aligned.m8n8.x4.shared.b16 {%0,%1,%2,%3}, [%4];\n"
        : "=r"(r[0]), "=r"(r[1]), "=r"(r[2]), "=r"(r[3]) : "r"(addr));
}

__device__ __forceinline__ void ldsm_x4_t(uint32_t* r, uint32_t addr) {
    asm volatile("ldmatrix.sync.aligned.m8n8.x4.trans.shared.b16 {%0,%1,%2,%3}, [%4];\n"
        : "=r"(r[0]), "=r"(r[1]), "=r"(r[2]), "=r"(r[3]) : "r"(addr));
}

__device__ __forceinline__ void mma_f16(float* c, const uint32_t* a, const uint32_t* b) {
    asm volatile(
        "mma.sync.aligned.m16n8k16.row.col.f32.f16.f16.f32 "
        "{%0,%1,%2,%3}, {%4,%5,%6,%7}, {%8,%9}, {%0,%1,%2,%3};\n"
        : "+f"(c[0]), "+f"(c[1]), "+f"(c[2]), "+f"(c[3])
        : "r"(a[0]), "r"(a[1]), "r"(a[2]), "r"(a[3]), "r"(b[0]), "r"(b[1]));
}

__device__ __forceinline__ uint32_t pack_h2(float a, float b) {
    __half2 h = __float22half2_rn(make_float2(a, b));
    return *reinterpret_cast<uint32_t*>(&h);
}

// pack float pair -> (hi f16x2, lo f16x2) (used for P split in flash)
__device__ __forceinline__ void split_pair(float a, float b, uint32_t& hu, uint32_t& lu) {
    __half2 h = __float22half2_rn(make_float2(a, b));
    float2 back = __half22float2(h);
    __half2 l = __float22half2_rn(make_float2(a - back.x, b - back.y));
    hu = *reinterpret_cast<uint32_t*>(&h);
    lu = *reinterpret_cast<uint32_t*>(&l);
}

__device__ __forceinline__ float gelu_exact(float a) {
    return 0.5f * a * (1.0f + erff(a * 0.70710678118654752f));
}

// ---------------------------------------------------------------------------
// Scratch (device globals; allocation-free per harness rules)
// ---------------------------------------------------------------------------
__device__ __align__(256) f16 g_xrot[TOK*EMB];
__device__ __align__(256) f16 g_xf[TOK*EMB];
__device__ __align__(256) f16 g_q[TOK*EMB];
__device__ __align__(256) f16 g_k[TOK*KVW];
__device__ __align__(256) f16 g_v[TOK*KVW];
__device__ __align__(256) f16 g_ctx[TOK*EMB];
__device__ __align__(256) float g_attn[TOK*EMB];
__device__ __align__(256) float g_h[TOK*EMB];
__device__ __align__(256) f16 g_h16[TOK*EMB];
__device__ __align__(256) f16 g_act[(size_t)TOK*FFN];
__device__ __align__(256) float g_fc[TOK*EMB];
__device__ __align__(256) float g_ropec[SEQ*64];
__device__ __align__(256) float g_ropes[SEQ*64];
// transposed weights, fp16 (B-side of all GEMMs)
__device__ __align__(256) f16 g_wqT[EMB*EMB];
__device__ __align__(256) f16 g_wkT[KVW*EMB];
__device__ __align__(256) f16 g_wvT[KVW*EMB];
__device__ __align__(256) f16 g_woT[EMB*EMB];
__device__ __align__(256) f16 g_winT[(size_t)2*FFN*EMB];
__device__ __align__(256) f16 g_woutT[(size_t)EMB*FFN];

// ---------------------------------------------------------------------------
// Transpose -> fp16, vectorized 8B stores; optional GeGLU row-interleave
// ---------------------------------------------------------------------------
__global__ __launch_bounds__(256) void transpose_h_kernel(
        const float* __restrict__ in, f16* __restrict__ hi,
        int R, int C, int ilv_half) {
    __shared__ float t[32][33];
    int bx = blockIdx.x * 32, by = blockIdx.y * 32;
    int tx = threadIdx.x & 31, ty8 = threadIdx.x >> 5;
    #pragma unroll
    for (int i = ty8; i < 32; i += 8)
        t[i][tx] = in[(size_t)(by + i) * C + bx + tx];
    __syncthreads();
    // write: thread -> out-row i (0..31), col quad u (0..7)
    int u = threadIdx.x & 7;
    int i = threadIdx.x >> 3;
    float v0 = t[4*u + 0][i], v1 = t[4*u + 1][i];
    float v2 = t[4*u + 2][i], v3 = t[4*u + 3][i];
    size_t r = (size_t)(bx + i);
    if (ilv_half) r = (r < (size_t)ilv_half) ? 2*r : 2*(r - ilv_half) + 1;
    uint2 p = make_uint2(pack_h2(v0, v1), pack_h2(v2, v3));
    *(uint2*)(hi + r * R + by + 4*u) = p;
}

// ---------------------------------------------------------------------------
// RoPE cos/sin table (SEQ x 64), built once per call (tiny)
// ---------------------------------------------------------------------------
__global__ __launch_bounds__(256) void rope_tab_kernel(float* __restrict__ tc,
                                                       float* __restrict__ ts) {
    int idx = blockIdx.x * 256 + threadIdx.x;
    if (idx >= SEQ * 64) return;
    int n = idx >> 6, j = idx & 63;
    // 10000^(-j/64) = 2^(-j * log2(10000)/64)
    float invf = exp2f(-(float)j * (13.287712379549449f / 64.f));
    float ang = (float)n * invf;
    float sv, cv;
    sincosf(ang, &sv, &cv);
    tc[idx] = cv; ts[idx] = sv;
}

// ---------------------------------------------------------------------------
// Fused RoPE + fp16 convert: reads x once, writes xrot (rotated) and xf (plain)
// ---------------------------------------------------------------------------
__global__ __launch_bounds__(256) void rope_fused_kernel(
        const float* __restrict__ x, const float* __restrict__ tc,
        const float* __restrict__ ts, f16* __restrict__ xrot,
        f16* __restrict__ xf) {
    int idx = blockIdx.x * 256 + threadIdx.x;
    if (idx >= TOK*EMB) return;
    int t = idx / EMB;
    int e = idx % EMB;
    int n = t % SEQ;
    int d = e % HDIM;
    int j; float partner; float sign;
    float xv = x[idx];
    if (d < 64) { j = d;      partner = x[idx + 64]; sign = -1.f; }
    else        { j = d - 64; partner = x[idx - 64]; sign =  1.f; }
    float c = tc[n * 64 + j], s = ts[n * 64 + j];
    xrot[idx] = __float2half_rn(xv * c + sign * partner * s);
    xf[idx]   = __float2half_rn(xv);
}

// ---------------------------------------------------------------------------
// Pure fp16 tensor-core GEMM: C = A @ B^T (1 HMMA per position).
// 128x128 tile, K-step 64 per stage (2 syncs per 64-K), 8 warps,
// 2-stage cp.async, 2 CTAs/SM.
// mode: 0 = fp32 C; 1 = f16 C; 2 = GeGLU epilogue -> f16 act width N/2.
// ---------------------------------------------------------------------------
#define WST_B    144               // 64 f16 = 128B data + 16 pad
#define OP_BYTES (128*WST_B)       // 18432
#define STAGE_B  (2*OP_BYTES)      // 36864 (A, B)
#define MG_SMEM  (2*STAGE_B)       // 73728 per CTA -> 2 CTAs/SM (147KB < 228KB)

__global__ __launch_bounds__(256, 2) void mma_gemm(
        const f16* __restrict__ A, const f16* __restrict__ B,
        float* __restrict__ C, f16* __restrict__ Ch,
        int M, int N, int K, int mode) {
    extern __shared__ char smem[];
    const uint32_t sb = smem_to_u32(smem);
    const int tid = threadIdx.x;
    const int m0 = blockIdx.x * 128, n0 = blockIdx.y * 128;
    const int warp = tid >> 5, lane = tid & 31;
    const int wm = warp & 1, wn = warp >> 1;

    const f16* srcs[2] = { A + (size_t)m0 * K, B + (size_t)n0 * K };

    float acc[4][4][4];
    #pragma unroll
    for (int i = 0; i < 4; i++)
        #pragma unroll
        for (int j = 0; j < 4; j++)
            #pragma unroll
            for (int r = 0; r < 4; r++) acc[i][j][r] = 0.f;

    const int S = K >> 6;
    const int lA_row = lane & 15, lA_k = lane >> 4;
    const int lB_row = ((lane >> 4) << 3) + (lane & 7);
    const int lB_k = (lane >> 3) & 1;

    auto issue_stage = [&](int s) {
        const uint32_t bufb = sb + (uint32_t)(s & 1) * STAGE_B;
        const int k0 = s << 6;
        #pragma unroll
        for (int it = 0; it < 8; it++) {
            int idx = tid + (it << 8);       // 0..2047
            int op = idx >> 10;              // 0=A,1=B
            int j = idx & 1023;
            int row = j >> 3, ch = j & 7;
            const f16* src = srcs[op] + (size_t)row * K + k0 + ch * 8;
            uint32_t dst = bufb + (uint32_t)(op * OP_BYTES + row * WST_B + ch * 16);
            CP_ASYNC16(dst, src);
        }
    };

    issue_stage(0); CP_COMMIT();

    for (int s = 0; s < S; s++) {
        if (s + 1 < S) {
            issue_stage(s + 1);
            CP_COMMIT();
            CP_WAIT(1);
        } else {
            CP_WAIT(0);
        }
        __syncthreads();

        const uint32_t base = sb + (uint32_t)(s & 1) * STAGE_B;
        #pragma unroll
        for (int k16 = 0; k16 < 4; k16++) {
            uint32_t bh[4][2];
            #pragma unroll
            for (int np = 0; np < 2; np++) {
                uint32_t rb = base + OP_BYTES
                            + (uint32_t)((wn * 32 + np * 16 + lB_row) * WST_B)
                            + k16 * 32 + lB_k * 16;
                uint32_t t4[4];
                ldsm_x4(t4, rb);
                bh[np*2][0] = t4[0]; bh[np*2][1] = t4[1];
                bh[np*2+1][0] = t4[2]; bh[np*2+1][1] = t4[3];
            }
            #pragma unroll
            for (int mt = 0; mt < 4; mt++) {
                uint32_t ah[4];
                uint32_t ra = base + (uint32_t)((wm * 64 + mt * 16 + lA_row) * WST_B)
                            + k16 * 32 + lA_k * 16;
                ldsm_x4(ah, ra);
                #pragma unroll
                for (int nt = 0; nt < 4; nt++)
                    mma_f16(acc[mt][nt], ah, bh[nt]);
            }
        }
        __syncthreads();
    }

    #pragma unroll
    for (int mt = 0; mt < 4; mt++) {
        int m = m0 + wm * 64 + mt * 16 + (lane >> 2);
        #pragma unroll
        for (int nt = 0; nt < 4; nt++) {
            int n = n0 + wn * 32 + nt * 8 + 2 * (lane & 3);
            if (mode == 0) {
                *(float2*)(C + (size_t)m * N + n) =
                    make_float2(acc[mt][nt][0], acc[mt][nt][1]);
                *(float2*)(C + (size_t)(m + 8) * N + n) =
                    make_float2(acc[mt][nt][2], acc[mt][nt][3]);
            } else if (mode == 1) {
                *(uint32_t*)(Ch + (size_t)m * N + n) =
                    pack_h2(acc[mt][nt][0], acc[mt][nt][1]);
                *(uint32_t*)(Ch + (size_t)(m + 8) * N + n) =
                    pack_h2(acc[mt][nt][2], acc[mt][nt][3]);
            } else {
                // GeGLU: (c0,c1)=(a,g) for row m; (c2,c3) for row m+8
                int Nh = N >> 1;
                int f = n >> 1;
                float v0 = gelu_exact(acc[mt][nt][0]) * acc[mt][nt][1];
                float v1 = gelu_exact(acc[mt][nt][2]) * acc[mt][nt][3];
                Ch[(size_t)m * Nh + f] = __float2half_rn(v0);
                Ch[(size_t)(m + 8) * Nh + f] = __float2half_rn(v1);
            }
        }
    }
}

// ---------------------------------------------------------------------------
// Tensor-core flash attention (fp16, causal, GQA) — unchanged from R16.
// ---------------------------------------------------------------------------
#define FSQ    0
#define FST0   34816
#define FSTAGE 34816          // per-stage: K, V each 64*272=17408
#define FV_OFF 17408
#define FL_SMEM (FST0 + 2*FSTAGE)   // 104448

__global__ __launch_bounds__(256) void flash_mma_kernel(
        const f16* __restrict__ Q, const f16* __restrict__ K,
        const f16* __restrict__ V, f16* __restrict__ O) {
    extern __shared__ char smem[];
    const uint32_t sb = smem_to_u32(smem);
    const int qt = (int)gridDim.x - 1 - (int)blockIdx.x;  // big tiles first
    const int hd = blockIdx.y, b = blockIdx.z;
    const int g = hd / (NHEAD / NGRP);
    const int tid = threadIdx.x;
    const int warp = tid >> 5, lane = tid & 31;
    const int lA_row = lane & 15, lA_k = lane >> 4;
    const int lB_row = ((lane >> 4) << 3) + (lane & 7);
    const int lB_k = (lane >> 3) & 1;
    const float SC = 0.08838834764831845f * 1.4426950408889634f;  // scale*log2e

    {
        const size_t qbase = ((size_t)(b * SEQ + qt * 128)) * EMB + hd * HDIM;
        #pragma unroll
        for (int it = 0; it < 8; it++) {
            int i = tid + (it << 8);
            int row = i >> 4, ch = i & 15;
            size_t ga = qbase + (size_t)row * EMB + ch * 8;
            *(uint4*)(smem + FSQ + row * 272 + ch * 16) = *(const uint4*)(Q + ga);
        }
    }

    auto issue_kv = [&](int kt) {
        const uint32_t stb = sb + FST0 + (uint32_t)(kt & 1) * FSTAGE;
        const size_t kbase = ((size_t)(b * SEQ + kt * 64)) * KVW + g * HDIM;
        #pragma unroll
        for (int it = 0; it < 8; it++) {
            int idx = tid + (it << 8);
            int arr = idx >> 10;           // 0=K,1=V
            int j = idx & 1023;
            int row = j >> 4, ch = j & 15;
            const f16* src = (arr ? V : K) + kbase + (size_t)row * KVW + ch * 8;
            uint32_t dst = stb + (uint32_t)arr * (uint32_t)FV_OFF
                         + (uint32_t)(row * 272 + ch * 16);
            CP_ASYNC16(dst, src);
        }
    };

    float o[16][4];
    #pragma unroll
    for (int i = 0; i < 16; i++)
        #pragma unroll
        for (int r = 0; r < 4; r++) o[i][r] = 0.f;
    float m0 = -1e30f, m1 = -1e30f, l0 = 0.f, l1 = 0.f;

    const int qg0 = qt * 128 + warp * 16 + (lane >> 2);
    const int qg1 = qg0 + 8;
    const int NT = 2 * qt + 2;

    issue_kv(0);
    CP_COMMIT();

    for (int kt = 0; kt < NT; kt++) {
        if (kt + 1 < NT) {
            issue_kv(kt + 1);
            CP_COMMIT();
            CP_WAIT(1);
        } else {
            CP_WAIT(0);
        }
        __syncthreads();
        const uint32_t stb = sb + FST0 + (uint32_t)(kt & 1) * FSTAGE;

        float s[8][4];
        #pragma unroll
        for (int j = 0; j < 8; j++)
            #pragma unroll
            for (int r = 0; r < 4; r++) s[j][r] = 0.f;

        #pragma unroll
        for (int ks = 0; ks < 8; ks++) {
            uint32_t q4[4];
            uint32_t ra = sb + FSQ + (uint32_t)((warp * 16 + lA_row) * 272)
                        + ks * 32 + lA_k * 16;
            ldsm_x4(q4, ra);
            #pragma unroll
            for (int np = 0; np < 4; np++) {
                uint32_t th[4];
                uint32_t rb = stb + (uint32_t)((np * 16 + lB_row) * 272)
                            + ks * 32 + lB_k * 16;
                ldsm_x4(th, rb);
                uint32_t bh0[2] = {th[0], th[1]}, bh1[2] = {th[2], th[3]};
                mma_f16(s[2*np],   q4, bh0);
                mma_f16(s[2*np+1], q4, bh1);
            }
        }

        float tm0 = -1e30f, tm1 = -1e30f;
        #pragma unroll
        for (int j = 0; j < 8; j++) {
            tm0 = fmaxf(tm0, fmaxf(s[j][0], s[j][1]));
            tm1 = fmaxf(tm1, fmaxf(s[j][2], s[j][3]));
        }
        tm0 = fmaxf(tm0, __shfl_xor_sync(0xffffffffu, tm0, 1));
        tm0 = fmaxf(tm0, __shfl_xor_sync(0xffffffffu, tm0, 2));
        tm1 = fmaxf(tm1, __shfl_xor_sync(0xffffffffu, tm1, 1));
        tm1 = fmaxf(tm1, __shfl_xor_sync(0xffffffffu, tm1, 2));
        float m0n = fmaxf(m0, tm0), m1n = fmaxf(m1, tm1);
        float c0 = exp2f((m0 - m0n) * SC), c1 = exp2f((m1 - m1n) * SC);

        const bool domask = (kt >= 2 * qt);
        float l0a = 0.f, l1a = 0.f;
        #pragma unroll
        for (int j = 0; j < 8; j++) {
            float p0 = exp2f((s[j][0] - m0n) * SC);
            float p1 = exp2f((s[j][1] - m0n) * SC);
            float p2 = exp2f((s[j][2] - m1n) * SC);
            float p3 = exp2f((s[j][3] - m1n) * SC);
            if (domask) {
                int colb = kt * 64 + j * 8 + 2 * (lane & 3);
                if (colb     > qg0) p0 = 0.f;
                if (colb + 1 > qg0) p1 = 0.f;
                if (colb     > qg1) p2 = 0.f;
                if (colb + 1 > qg1) p3 = 0.f;
            }
            s[j][0] = p0; s[j][1] = p1; s[j][2] = p2; s[j][3] = p3;
            l0a += p0 + p1; l1a += p2 + p3;
        }
        l0a += __shfl_xor_sync(0xffffffffu, l0a, 1);
        l0a += __shfl_xor_sync(0xffffffffu, l0a, 2);
        l1a += __shfl_xor_sync(0xffffffffu, l1a, 1);
        l1a += __shfl_xor_sync(0xffffffffu, l1a, 2);
        l0 = l0 * c0 + l0a;
        l1 = l1 * c1 + l1a;
        m0 = m0n; m1 = m1n;

        #pragma unroll
        for (int i = 0; i < 16; i++) {
            o[i][0] *= c0; o[i][1] *= c0; o[i][2] *= c1; o[i][3] *= c1;
        }

        #pragma unroll
        for (int ks = 0; ks < 4; ks++) {
            uint32_t ah[4], al[4];
            split_pair(s[2*ks][0],   s[2*ks][1],   ah[0], al[0]);
            split_pair(s[2*ks][2],   s[2*ks][3],   ah[1], al[1]);
            split_pair(s[2*ks+1][0], s[2*ks+1][1], ah[2], al[2]);
            split_pair(s[2*ks+1][2], s[2*ks+1][3], ah[3], al[3]);
            #pragma unroll
            for (int dp = 0; dp < 8; dp++) {
                uint32_t th[4];
                uint32_t rb = stb + FV_OFF
                            + (uint32_t)((ks * 16 + (lane & 15)) * 272)
                            + (uint32_t)((dp * 16 + ((lane >> 4) << 3)) * 2);
                ldsm_x4_t(th, rb);
                uint32_t bh0[2] = {th[0], th[1]}, bh1[2] = {th[2], th[3]};
                mma_f16(o[2*dp],   ah, bh0);
                mma_f16(o[2*dp],   al, bh0);
                mma_f16(o[2*dp+1], ah, bh1);
                mma_f16(o[2*dp+1], al, bh1);
            }
        }
        __syncthreads();
    }

    float inv0 = 1.f / l0, inv1 = 1.f / l1;
    const size_t tok0 = (size_t)(b * SEQ + qt * 128 + warp * 16 + (lane >> 2));
    #pragma unroll
    for (int dt = 0; dt < 16; dt++) {
        int col = hd * HDIM + dt * 8 + 2 * (lane & 3);
        *(uint32_t*)(O + tok0 * EMB + col) =
            pack_h2(o[dt][0] * inv0, o[dt][1] * inv0);
        *(uint32_t*)(O + (tok0 + 8) * EMB + col) =
            pack_h2(o[dt][2] * inv1, o[dt][3] * inv1);
    }
}

// ---------------------------------------------------------------------------
// out = rmsnorm(a + b) * w ; optional f16 output
// ---------------------------------------------------------------------------
__global__ __launch_bounds__(256) void add_rmsnorm_kernel(const float* __restrict__ a,
                                                          const float* __restrict__ b,
                                                          const float* __restrict__ w,
                                                          float* __restrict__ out,
                                                          f16* __restrict__ oh) {
    int row = blockIdx.x;
    const float4* a4 = (const float4*)(a + (size_t)row * EMB);
    const float4* b4 = (const float4*)(b + (size_t)row * EMB);
    const float4* w4 = (const float4*)w;
    float4* o4 = (float4*)(out + (size_t)row * EMB);

    float4 s[2];
    float ss = 0.f;
    #pragma unroll
    for (int i = 0; i < 2; i++) {
        float4 av = a4[threadIdx.x + i * 256];
        float4 bv = b4[threadIdx.x + i * 256];
        s[i] = make_float4(av.x + bv.x, av.y + bv.y, av.z + bv.z, av.w + bv.w);
        ss += s[i].x * s[i].x + s[i].y * s[i].y + s[i].z * s[i].z + s[i].w * s[i].w;
    }
    __shared__ float red[8];
    for (int o = 16; o > 0; o >>= 1) ss += __shfl_xor_sync(0xffffffff, ss, o);
    if ((threadIdx.x & 31) == 0) red[threadIdx.x >> 5] = ss;
    __syncthreads();
    __shared__ float total_s;
    if (threadIdx.x == 0) {
        float t = 0.f;
        #pragma unroll
        for (int i = 0; i < 8; i++) t += red[i];
        total_s = t;
    }
    __syncthreads();
    float rstd = rsqrtf(total_s / (float)EMB + 1e-6f);
    #pragma unroll
    for (int i = 0; i < 2; i++) {
        float4 wv = w4[threadIdx.x + i * 256];
        float4 ov = make_float4(s[i].x * rstd * wv.x, s[i].y * rstd * wv.y,
                                s[i].z * rstd * wv.z, s[i].w * rstd * wv.w);
        o4[threadIdx.x + i * 256] = ov;
        if (oh) {
            size_t base = (size_t)row * EMB + (threadIdx.x + i * 256) * 4;
            *(uint32_t*)(oh + base)     = pack_h2(ov.x, ov.y);
            *(uint32_t*)(oh + base + 2) = pack_h2(ov.z, ov.w);
        }
    }
}

// ---------------------------------------------------------------------------
// Launch
// ---------------------------------------------------------------------------
extern "C" void kernel_launch(void* const* d_in, const int* in_sizes, int n_in,
                              void* d_out, int out_size) {
    const float* x       = (const float*)d_in[0];
    const float* wq      = (const float*)d_in[1];
    const float* wk      = (const float*)d_in[2];
    const float* wv      = (const float*)d_in[3];
    const float* wo      = (const float*)d_in[4];
    const float* norm1_w = (const float*)d_in[5];
    const float* norm2_w = (const float*)d_in[6];
    const float* w_in    = (const float*)d_in[7];
    const float* w_out   = (const float*)d_in[8];
    float* out = (float*)d_out;

    f16 *xrot, *xf, *q, *k, *v, *ctx, *h16, *act;
    f16 *wqT, *wkT, *wvT, *woT, *winT, *woutT;
    float *attn, *h, *fc, *ropec, *ropes;
    cudaGetSymbolAddress((void**)&xrot, g_xrot);
    cudaGetSymbolAddress((void**)&xf,   g_xf);
    cudaGetSymbolAddress((void**)&q,    g_q);
    cudaGetSymbolAddress((void**)&k,    g_k);
    cudaGetSymbolAddress((void**)&v,    g_v);
    cudaGetSymbolAddress((void**)&ctx,  g_ctx);
    cudaGetSymbolAddress((void**)&attn, g_attn);
    cudaGetSymbolAddress((void**)&h,    g_h);
    cudaGetSymbolAddress((void**)&h16,  g_h16);
    cudaGetSymbolAddress((void**)&act,  g_act);
    cudaGetSymbolAddress((void**)&fc,   g_fc);
    cudaGetSymbolAddress((void**)&ropec,g_ropec);
    cudaGetSymbolAddress((void**)&ropes,g_ropes);
    cudaGetSymbolAddress((void**)&wqT,  g_wqT);
    cudaGetSymbolAddress((void**)&wkT,  g_wkT);
    cudaGetSymbolAddress((void**)&wvT,  g_wvT);
    cudaGetSymbolAddress((void**)&woT,  g_woT);
    cudaGetSymbolAddress((void**)&winT, g_winT);
    cudaGetSymbolAddress((void**)&woutT,g_woutT);

    cudaFuncSetAttribute(mma_gemm, cudaFuncAttributeMaxDynamicSharedMemorySize,
                         MG_SMEM);
    cudaFuncSetAttribute(flash_mma_kernel, cudaFuncAttributeMaxDynamicSharedMemorySize,
                         FL_SMEM);

    // 0. Transpose weights -> [N][K] fp16 (w_in rows interleaved a/g)
    transpose_h_kernel<<<dim3(EMB/32,   EMB/32), 256>>>(wq,    wqT,   EMB, EMB, 0);
    transpose_h_kernel<<<dim3(KVW/32,   EMB/32), 256>>>(wk,    wkT,   EMB, KVW, 0);
    transpose_h_kernel<<<dim3(KVW/32,   EMB/32), 256>>>(wv,    wvT,   EMB, KVW, 0);
    transpose_h_kernel<<<dim3(EMB/32,   EMB/32), 256>>>(wo,    woT,   EMB, EMB, 0);
    transpose_h_kernel<<<dim3(2*FFN/32, EMB/32), 256>>>(w_in,  winT,  EMB, 2*FFN, FFN);
    transpose_h_kernel<<<dim3(EMB/32,   FFN/32), 256>>>(w_out, woutT, FFN, EMB, 0);

    // 1. RoPE table + fused rope/cvt (x read once)
    rope_tab_kernel<<<(SEQ * 64 + 255) / 256, 256>>>(ropec, ropes);
    rope_fused_kernel<<<(TOK * EMB + 255) / 256, 256>>>(x, ropec, ropes, xrot, xf);

    // 2-4. Q/K/V projections -> f16
    mma_gemm<<<dim3(TOK/128, EMB/128), 256, MG_SMEM>>>(xrot, wqT,
        nullptr, q, TOK, EMB, EMB, 1);
    mma_gemm<<<dim3(TOK/128, KVW/128), 256, MG_SMEM>>>(xrot, wkT,
        nullptr, k, TOK, KVW, EMB, 1);
    mma_gemm<<<dim3(TOK/128, KVW/128), 256, MG_SMEM>>>(xf,   wvT,
        nullptr, v, TOK, KVW, EMB, 1);

    // 5. Flash attention -> ctx f16
    flash_mma_kernel<<<dim3(SEQ/128, NHEAD, BATCH), 256, FL_SMEM>>>(q, k, v, ctx);

    // 6. Output projection (fp32 out)
    mma_gemm<<<dim3(TOK/128, EMB/128), 256, MG_SMEM>>>(ctx, woT,
        attn, nullptr, TOK, EMB, EMB, 0);

    // 7. h = rmsnorm(x + attn) * norm1_w (+ f16 copy)
    add_rmsnorm_kernel<<<TOK, 256>>>(x, attn, norm1_w, h, h16);

    // 8+9. act = geglu(h @ w_in) fused (w_in rows interleaved a/g)
    mma_gemm<<<dim3(TOK/128, 2*FFN/128), 256, MG_SMEM>>>(h16, winT,
        nullptr, act, TOK, 2*FFN, EMB, 2);

    // 10. fc = act @ w_out (fp32 out)
    mma_gemm<<<dim3(TOK/128, EMB/128), 256, MG_SMEM>>>(act, woutT,
        fc, nullptr, TOK, EMB, FFN, 0);

    // 11. out = rmsnorm(h + fc) * norm2_w
    add_rmsnorm_kernel<<<TOK, 256>>>(h, fc, norm2_w, out, nullptr);
}